// round 4
// baseline (speedup 1.0000x reference)
#include <cuda_runtime.h>
#include <cuda_bf16.h>
#include <cstddef>

#define Bb 4
#define Nn 4096
#define DIMV 512
#define Hh 8
#define Dd 64
#define Mm 256
#define BHc 32
#define QSCALE 0.125f

// ---------------- scratch (bf16 where possible) ----------------
__device__ __nv_bfloat16 g_q   [BHc*Nn*Dd];
__device__ __nv_bfloat16 g_k   [BHc*Nn*Dd];
__device__ __nv_bfloat16 g_v   [BHc*Nn*Dd];
__device__ __nv_bfloat16 g_ql  [BHc*Mm*Dd];
__device__ __nv_bfloat16 g_kl  [BHc*Mm*Dd];
__device__ float         g_a2f [BHc*Mm*Mm];   // fp32 scores / softmaxed a2
__device__ __nv_bfloat16 g_a2h [BHc*Mm*Mm];
__device__ __nv_bfloat16 g_z   [BHc*Mm*Mm];
__device__ __nv_bfloat16 g_zn  [BHc*Mm*Mm];
__device__ __nv_bfloat16 g_az  [BHc*Mm*Mm];
__device__ __nv_bfloat16 g_w1  [BHc*Mm*Mm];
__device__ __nv_bfloat16 g_w2  [BHc*Mm*Mm];
__device__ __nv_bfloat16 g_a3v [BHc*Mm*Dd];
__device__ __nv_bfloat16 g_wm  [BHc*Mm*Dd];
__device__ __nv_bfloat16 g_outh[BHc*Nn*Dd];
__device__ float g_mu[Bb*Nn];
__device__ float g_rs[Bb*Nn];
__device__ float g_ms1, g_ms2;

__device__ __forceinline__ unsigned packbf(float a, float b) {
    __nv_bfloat162 t = __floats2bfloat162_rn(a, b);
    return *reinterpret_cast<unsigned*>(&t);
}
__device__ __forceinline__ float2 unpackbf(unsigned u) {
    __nv_bfloat162 t = *reinterpret_cast<__nv_bfloat162*>(&u);
    return make_float2(__bfloat162float(t.x), __bfloat162float(t.y));
}
__device__ __forceinline__ void mma16(float* c, const unsigned* a, const unsigned* b) {
    asm volatile("mma.sync.aligned.m16n8k16.row.col.f32.bf16.bf16.f32 "
                 "{%0,%1,%2,%3},{%4,%5,%6,%7},{%8,%9},{%0,%1,%2,%3};"
                 : "+f"(c[0]), "+f"(c[1]), "+f"(c[2]), "+f"(c[3])
                 : "r"(a[0]), "r"(a[1]), "r"(a[2]), "r"(a[3]), "r"(b[0]), "r"(b[1]));
}

// ---------------- small kernels ----------------
__global__ void k_init() { g_ms1 = 0.f; g_ms2 = 0.f; }

__global__ void k_lnstats(const float* __restrict__ x) {
    int r = blockIdx.x, t = threadIdx.x;
    const float* xp = x + (size_t)r * DIMV;
    float v0 = xp[t], v1 = xp[t + 256];
    __shared__ float red[256];
    red[t] = v0 + v1; __syncthreads();
    for (int s = 128; s; s >>= 1) { if (t < s) red[t] += red[t + s]; __syncthreads(); }
    float mean = red[0] * (1.f / 512.f);
    __syncthreads();
    float d0 = v0 - mean, d1 = v1 - mean;
    red[t] = d0 * d0 + d1 * d1; __syncthreads();
    for (int s = 128; s; s >>= 1) { if (t < s) red[t] += red[t + s]; __syncthreads(); }
    if (t == 0) { g_mu[r] = mean; g_rs[r] = rsqrtf(red[0] * (1.f / 512.f) + 1e-5f); }
}

// landmark means from bf16 q/k (pairwise)
__global__ void k_land() {
    int idx = blockIdx.x * 256 + threadIdx.x;    // < 2*32*256*32
    int sel = idx >= (BHc * Mm * 32);
    int e = idx & (BHc * Mm * 32 - 1);
    int bh = e >> 13, j = (e >> 5) & 255, dp = e & 31;
    const __nv_bfloat16* src = sel ? g_k : g_q;
    const __nv_bfloat16* p = src + ((size_t)bh * 4096 + j * 16) * 64 + dp * 2;
    float s0 = 0.f, s1 = 0.f;
#pragma unroll
    for (int t = 0; t < 16; t++) {
        float2 f = unpackbf(*(const unsigned*)(p + t * 64));
        s0 += f.x; s1 += f.y;
    }
    __nv_bfloat16* dst = sel ? g_kl : g_ql;
    *(unsigned*)(dst + (size_t)bh * 16384 + j * 64 + dp * 2) =
        packbf(s0 * (1.f / 16.f), s1 * (1.f / 16.f));
}

__global__ void k_softmax1(float* __restrict__ p) {
    int row = blockIdx.x, t = threadIdx.x;
    p += (size_t)row * 256;
    float rv = p[t];
    __shared__ float red[256];
    red[t] = rv; __syncthreads();
    for (int s = 128; s; s >>= 1) { if (t < s) red[t] = fmaxf(red[t], red[t + s]); __syncthreads(); }
    float m = red[0]; __syncthreads();
    rv = __expf(rv - m);
    red[t] = rv; __syncthreads();
    for (int s = 128; s; s >>= 1) { if (t < s) red[t] += red[t + s]; __syncthreads(); }
    p[t] = rv / red[0];
}

__global__ void k_sums(const float* __restrict__ a) {
    int mat = blockIdx.x, t = threadIdx.x;
    const float* A = a + (size_t)mat * 65536;
    float cs = 0.f, rs = 0.f;
    for (int i = 0; i < 256; i++) { cs += A[i * 256 + t]; rs += A[t * 256 + i]; }
    __shared__ float red[256];
    red[t] = rs; __syncthreads();
    for (int s = 128; s; s >>= 1) { if (t < s) red[t] = fmaxf(red[t], red[t + s]); __syncthreads(); }
    if (!t) atomicMax((int*)&g_ms1, __float_as_int(red[0]));
    __syncthreads();
    red[t] = cs; __syncthreads();
    for (int s = 128; s; s >>= 1) { if (t < s) red[t] = fmaxf(red[t], red[t + s]); __syncthreads(); }
    if (!t) atomicMax((int*)&g_ms2, __float_as_int(red[0]));
}

// z = a2^T / (ms1*ms2) in bf16; also a2h = bf16(a2)
__global__ void k_z0() {
    int p = blockIdx.x * 256 + threadIdx.x;      // pair index < 32*32768
    float inv = 1.f / (g_ms1 * g_ms2);
    int mat = p >> 15, rem = p & 32767;
    int r = rem >> 7, cp = (rem & 127) * 2;
    const float* A = g_a2f + ((size_t)mat << 16);
    float t0 = A[(size_t)cp * 256 + r], t1 = A[(size_t)(cp + 1) * 256 + r];
    *(unsigned*)(g_z + ((size_t)mat << 16) + (size_t)r * 256 + cp) = packbf(t0 * inv, t1 * inv);
    float2 s = *(const float2*)(A + (size_t)r * 256 + cp);
    *(unsigned*)(g_a2h + ((size_t)mat << 16) + (size_t)r * 256 + cp) = packbf(s.x, s.y);
}

// depthwise conv residual, bf16 v -> add into bf16 outh
__global__ void k_conv2(const float* __restrict__ w) {
    int nt = blockIdx.x, bh = blockIdx.y;
    __shared__ float vs[160][64];
    const __nv_bfloat16* vp = g_v + ((size_t)bh << 18);
    int n0 = nt * 128;
    for (int i = threadIdx.x; i < 160 * 8; i += 256) {
        int r = i >> 3, g = i & 7;
        int n = n0 - 16 + r;
        if (n >= 0 && n < 4096) {
            uint4 u = *(const uint4*)(vp + (size_t)n * 64 + g * 8);
            float2 f0 = unpackbf(u.x), f1 = unpackbf(u.y), f2 = unpackbf(u.z), f3 = unpackbf(u.w);
            vs[r][g * 8 + 0] = f0.x; vs[r][g * 8 + 1] = f0.y;
            vs[r][g * 8 + 2] = f1.x; vs[r][g * 8 + 3] = f1.y;
            vs[r][g * 8 + 4] = f2.x; vs[r][g * 8 + 5] = f2.y;
            vs[r][g * 8 + 6] = f3.x; vs[r][g * 8 + 7] = f3.y;
        } else {
#pragma unroll
            for (int q = 0; q < 8; q++) vs[r][g * 8 + q] = 0.f;
        }
    }
    __syncthreads();
    int h = bh & 7;
    float wr[33];
#pragma unroll
    for (int t = 0; t < 33; t++) wr[t] = w[h * 33 + t];
    int dp = threadIdx.x & 31, nl = threadIdx.x >> 5;
    for (int p = 0; p < 16; p++) {
        int n = nl + p * 8;
        float a0 = 0.f, a1 = 0.f;
#pragma unroll
        for (int t = 0; t < 33; t++) {
            a0 += wr[t] * vs[n + t][dp * 2];
            a1 += wr[t] * vs[n + t][dp * 2 + 1];
        }
        unsigned* op = (unsigned*)(g_outh + ((size_t)bh * 4096 + n0 + n) * 64 + dp * 2);
        float2 o = unpackbf(*op);
        *op = packbf(o.x + a0, o.y + a1);
    }
}

// ---------------- bf16 tensor-core batched GEMM ----------------
// tile 128x64, K-tile 32, 8 warps; smem holds packed bf16 pairs along K.
// aMode: 0=bf16 rows, 1=fp32+LN(x), 2=outh head-merge
// bMode: 0=fp32 trans0 (B[k][n]), 1=bf16 trans0, 2=bf16 trans1 (B[n][k])
// outMode: 0=bf16 C (+cA*AE), 1=qkv split, 2=fp32 C (+bias,+resid)
__global__ __launch_bounds__(256) void tgemm(
    const void* Av, const void* Bv, void* Cv, int Kr,
    int lda, int ldb, int ldc, long sA, long sB, long sC,
    int aMode, int bMode, int outMode,
    float cM, float cA, const __nv_bfloat16* __restrict__ AE,
    const float* __restrict__ bias, const float* __restrict__ resid,
    const float* __restrict__ gammaP, const float* __restrict__ betaP) {
    int bz = blockIdx.z;
    const __nv_bfloat16* Ab = (const __nv_bfloat16*)Av + (size_t)bz * sA;
    const float*         Af = (const float*)Av + (size_t)bz * sA;
    const __nv_bfloat16* Bh = (const __nv_bfloat16*)Bv + (size_t)bz * sB;
    const float*         Bf = (const float*)Bv + (size_t)bz * sB;
    __nv_bfloat16*       Cb = (__nv_bfloat16*)Cv + (size_t)bz * sC;
    float*               Cf = (float*)Cv + (size_t)bz * sC;

    __shared__ unsigned As[128][17];
    __shared__ unsigned Bs[64][17];

    int tid = threadIdx.x, lane = tid & 31, w = tid >> 5;
    int wr = w >> 1, wc = w & 1;
    int rowBase = blockIdx.y * 128, colBase = blockIdx.x * 64;
    int r0 = lane >> 2, kq = lane & 3;

    float acc[2][4][4];
#pragma unroll
    for (int mi = 0; mi < 2; mi++)
#pragma unroll
        for (int ni = 0; ni < 4; ni++)
#pragma unroll
            for (int q = 0; q < 4; q++) acc[mi][ni][q] = 0.f;

    for (int k0 = 0; k0 < Kr; k0 += 32) {
        // ---- A tile (128 x 32 -> 16 pairs) ----
        {
            int r = tid >> 1, h = tid & 1;
            unsigned* dst = &As[r][h * 8];
            if (aMode == 0) {
                const __nv_bfloat16* ap = Ab + (size_t)(rowBase + r) * lda + k0 + h * 16;
                uint4 u0 = *(const uint4*)ap;
                uint4 u1 = *(const uint4*)(ap + 8);
                dst[0] = u0.x; dst[1] = u0.y; dst[2] = u0.z; dst[3] = u0.w;
                dst[4] = u1.x; dst[5] = u1.y; dst[6] = u1.z; dst[7] = u1.w;
            } else if (aMode == 1) {
                int gr = rowBase + r;
                float mu = g_mu[gr], rsd = g_rs[gr];
                const float* ap = Af + (size_t)gr * lda + k0 + h * 16;
                const float* gp = gammaP + k0 + h * 16;
                const float* bp = betaP + k0 + h * 16;
#pragma unroll
                for (int i = 0; i < 4; i++) {
                    float4 a4 = ((const float4*)ap)[i];
                    float4 g4 = ((const float4*)gp)[i];
                    float4 b4 = ((const float4*)bp)[i];
                    float n0 = (a4.x - mu) * rsd * g4.x + b4.x;
                    float n1 = (a4.y - mu) * rsd * g4.y + b4.y;
                    float n2 = (a4.z - mu) * rsd * g4.z + b4.z;
                    float n3 = (a4.w - mu) * rsd * g4.w + b4.w;
                    dst[i * 2]     = packbf(n0, n1);
                    dst[i * 2 + 1] = packbf(n2, n3);
                }
            } else {
                int gr = rowBase + r;
                int b = gr >> 12, n = gr & 4095;
                int kk = k0 + h * 16;
                int hh = kk >> 6, d = kk & 63;
                const __nv_bfloat16* ap = g_outh + (((size_t)(b * 8 + hh)) * 4096 + n) * 64 + d;
                uint4 u0 = *(const uint4*)ap;
                uint4 u1 = *(const uint4*)(ap + 8);
                dst[0] = u0.x; dst[1] = u0.y; dst[2] = u0.z; dst[3] = u0.w;
                dst[4] = u1.x; dst[5] = u1.y; dst[6] = u1.z; dst[7] = u1.w;
            }
        }
        // ---- B tile (32k x 64n -> Bs[n][kpair]) ----
        if (bMode == 2) {
            int n = tid >> 2, q = tid & 3;
            const __nv_bfloat16* bp = Bh + (size_t)(colBase + n) * ldb + k0 + q * 8;
            uint4 u = *(const uint4*)bp;
            unsigned* d = &Bs[n][q * 4];
            d[0] = u.x; d[1] = u.y; d[2] = u.z; d[3] = u.w;
        } else if (bMode == 0) {
            int kp = tid >> 4, n0 = (tid & 15) * 4;
            const float* bp = Bf + (size_t)(k0 + 2 * kp) * ldb + colBase + n0;
            float4 r1 = *(const float4*)bp;
            float4 r2 = *(const float4*)(bp + ldb);
            Bs[n0 + 0][kp] = packbf(r1.x, r2.x);
            Bs[n0 + 1][kp] = packbf(r1.y, r2.y);
            Bs[n0 + 2][kp] = packbf(r1.z, r2.z);
            Bs[n0 + 3][kp] = packbf(r1.w, r2.w);
        } else {
            int kp = tid >> 4, n0 = (tid & 15) * 4;
            const __nv_bfloat16* bp = Bh + (size_t)(k0 + 2 * kp) * ldb + colBase + n0;
            uint2 r1 = *(const uint2*)bp;
            uint2 r2 = *(const uint2*)(bp + ldb);
            Bs[n0 + 0][kp] = __byte_perm(r1.x, r2.x, 0x5410);
            Bs[n0 + 1][kp] = __byte_perm(r1.x, r2.x, 0x7632);
            Bs[n0 + 2][kp] = __byte_perm(r1.y, r2.y, 0x5410);
            Bs[n0 + 3][kp] = __byte_perm(r1.y, r2.y, 0x7632);
        }
        __syncthreads();

#pragma unroll
        for (int ks = 0; ks < 2; ks++) {
            int kb = ks * 8;
            unsigned ar[2][4], br[4][2];
#pragma unroll
            for (int mi = 0; mi < 2; mi++) {
                int r = wr * 32 + mi * 16 + r0;
                ar[mi][0] = As[r][kb + kq];
                ar[mi][1] = As[r + 8][kb + kq];
                ar[mi][2] = As[r][kb + kq + 4];
                ar[mi][3] = As[r + 8][kb + kq + 4];
            }
#pragma unroll
            for (int ni = 0; ni < 4; ni++) {
                int n = wc * 32 + ni * 8 + r0;
                br[ni][0] = Bs[n][kb + kq];
                br[ni][1] = Bs[n][kb + kq + 4];
            }
#pragma unroll
            for (int mi = 0; mi < 2; mi++)
#pragma unroll
                for (int ni = 0; ni < 4; ni++) mma16(acc[mi][ni], ar[mi], br[ni]);
        }
        __syncthreads();
    }

    // ---- epilogue ----
#pragma unroll
    for (int mi = 0; mi < 2; mi++) {
#pragma unroll
        for (int ni = 0; ni < 4; ni++) {
            int rr = rowBase + wr * 32 + mi * 16 + r0;
            int cc = colBase + wc * 32 + ni * 8 + kq * 2;
#pragma unroll
            for (int hf = 0; hf < 2; hf++) {
                int r = rr + hf * 8;
                float v0 = cM * acc[mi][ni][hf * 2];
                float v1 = cM * acc[mi][ni][hf * 2 + 1];
                if (outMode == 0) {
                    if (AE) {
                        unsigned ae = *(const unsigned*)(AE + (size_t)bz * sA + (size_t)r * lda + cc);
                        float2 f = unpackbf(ae);
                        v0 += cA * f.x; v1 += cA * f.y;
                    }
                    *(unsigned*)(Cb + (size_t)r * ldc + cc) = packbf(v0, v1);
                } else if (outMode == 1) {
                    int which = cc >> 9, inner = cc & 511;
                    int hh = inner >> 6, d = inner & 63;
                    int b = r >> 12, n = r & 4095;
                    size_t dst = (((size_t)(b * 8 + hh)) * 4096 + n) * 64 + d;
                    if (which == 0)      *(unsigned*)(g_q + dst) = packbf(v0 * QSCALE, v1 * QSCALE);
                    else if (which == 1) *(unsigned*)(g_k + dst) = packbf(v0, v1);
                    else                 *(unsigned*)(g_v + dst) = packbf(v0, v1);
                } else {
                    if (bias) { v0 += bias[cc]; v1 += bias[cc + 1]; }
                    if (resid) {
                        float2 rx = *(const float2*)(resid + (size_t)r * ldc + cc);
                        v0 += rx.x; v1 += rx.y;
                    }
                    *(float2*)(Cf + (size_t)r * ldc + cc) = make_float2(v0, v1);
                }
            }
        }
    }
}

// ---------------- flash-style attn3 @ v (bf16) ----------------
// grid (4, 32), 128 threads; smem u32: Qs[64*33] Ks[64*33] Vt[64*33] Ps[64*33]
__global__ __launch_bounds__(128) void k_flash() {
    int rt = blockIdx.x, bh = blockIdx.y;
    extern __shared__ unsigned sm[];
    unsigned* Qs = sm;
    unsigned* Ks = sm + 2112;
    unsigned* Vt = sm + 4224;
    unsigned* Ps = sm + 6336;
    const __nv_bfloat16* qlp = g_ql + (size_t)bh * 16384 + (size_t)rt * 64 * 64;
    const __nv_bfloat16* kp  = g_k + ((size_t)bh << 18);
    const __nv_bfloat16* vp  = g_v + ((size_t)bh << 18);
    int tid = threadIdx.x, lane = tid & 31, w = tid >> 5;
    int r0 = lane >> 2, kq = lane & 3;
    int wrow = w * 16;

    {
        int r = tid >> 1, h = tid & 1;
        const __nv_bfloat16* ap = qlp + r * 64 + h * 32;
        unsigned* dst = &Qs[r * 33 + h * 16];
#pragma unroll
        for (int i = 0; i < 4; i++) {
            uint4 u = ((const uint4*)ap)[i];
            dst[i * 4] = u.x; dst[i * 4 + 1] = u.y; dst[i * 4 + 2] = u.z; dst[i * 4 + 3] = u.w;
        }
    }

    float O[8][4];
#pragma unroll
    for (int j = 0; j < 8; j++)
#pragma unroll
        for (int q = 0; q < 4; q++) O[j][q] = 0.f;
    float m0 = -1e30f, m1 = -1e30f, l0 = 0.f, l1 = 0.f;

    for (int n0 = 0; n0 < 4096; n0 += 64) {
        __syncthreads();
        {
            int r = tid >> 1, h = tid & 1;
            const __nv_bfloat16* ap = kp + (size_t)(n0 + r) * 64 + h * 32;
            unsigned* dst = &Ks[r * 33 + h * 16];
#pragma unroll
            for (int i = 0; i < 4; i++) {
                uint4 u = ((const uint4*)ap)[i];
                dst[i * 4] = u.x; dst[i * 4 + 1] = u.y; dst[i * 4 + 2] = u.z; dst[i * 4 + 3] = u.w;
            }
        }
#pragma unroll
        for (int it = 0; it < 2; it++) {
            int i = tid + it * 128;
            int sp = i >> 3, dg = i & 7;
            const __nv_bfloat16* ap = vp + (size_t)(n0 + 2 * sp) * 64 + dg * 8;
            uint4 ua = *(const uint4*)ap;
            uint4 ub = *(const uint4*)(ap + 64);
            unsigned av[4] = {ua.x, ua.y, ua.z, ua.w};
            unsigned bv[4] = {ub.x, ub.y, ub.z, ub.w};
#pragma unroll
            for (int q2 = 0; q2 < 4; q2++) {
                int d0 = dg * 8 + q2 * 2;
                Vt[d0 * 33 + sp]       = __byte_perm(av[q2], bv[q2], 0x5410);
                Vt[(d0 + 1) * 33 + sp] = __byte_perm(av[q2], bv[q2], 0x7632);
            }
        }
        __syncthreads();

        float sc[8][4];
#pragma unroll
        for (int j = 0; j < 8; j++)
#pragma unroll
            for (int q = 0; q < 4; q++) sc[j][q] = 0.f;
#pragma unroll
        for (int ks = 0; ks < 4; ks++) {
            int kb = ks * 8;
            unsigned a[4];
            a[0] = Qs[(wrow + r0) * 33 + kb + kq];
            a[1] = Qs[(wrow + r0 + 8) * 33 + kb + kq];
            a[2] = Qs[(wrow + r0) * 33 + kb + kq + 4];
            a[3] = Qs[(wrow + r0 + 8) * 33 + kb + kq + 4];
#pragma unroll
            for (int j = 0; j < 8; j++) {
                unsigned b[2] = { Ks[(j * 8 + r0) * 33 + kb + kq],
                                  Ks[(j * 8 + r0) * 33 + kb + kq + 4] };
                mma16(sc[j], a, b);
            }
        }
        float tm0 = -1e30f, tm1 = -1e30f;
#pragma unroll
        for (int j = 0; j < 8; j++) {
            tm0 = fmaxf(tm0, fmaxf(sc[j][0], sc[j][1]));
            tm1 = fmaxf(tm1, fmaxf(sc[j][2], sc[j][3]));
        }
        tm0 = fmaxf(tm0, __shfl_xor_sync(0xffffffffu, tm0, 1));
        tm0 = fmaxf(tm0, __shfl_xor_sync(0xffffffffu, tm0, 2));
        tm1 = fmaxf(tm1, __shfl_xor_sync(0xffffffffu, tm1, 1));
        tm1 = fmaxf(tm1, __shfl_xor_sync(0xffffffffu, tm1, 2));
        float mn0 = fmaxf(m0, tm0), mn1 = fmaxf(m1, tm1);
        float al0 = __expf(m0 - mn0), al1 = __expf(m1 - mn1);
        float ts0 = 0.f, ts1 = 0.f;
#pragma unroll
        for (int j = 0; j < 8; j++) {
            sc[j][0] = __expf(sc[j][0] - mn0); sc[j][1] = __expf(sc[j][1] - mn0);
            sc[j][2] = __expf(sc[j][2] - mn1); sc[j][3] = __expf(sc[j][3] - mn1);
            ts0 += sc[j][0] + sc[j][1];
            ts1 += sc[j][2] + sc[j][3];
        }
        ts0 += __shfl_xor_sync(0xffffffffu, ts0, 1); ts0 += __shfl_xor_sync(0xffffffffu, ts0, 2);
        ts1 += __shfl_xor_sync(0xffffffffu, ts1, 1); ts1 += __shfl_xor_sync(0xffffffffu, ts1, 2);
        l0 = l0 * al0 + ts0; l1 = l1 * al1 + ts1;
        m0 = mn0; m1 = mn1;
#pragma unroll
        for (int j = 0; j < 8; j++) {
            O[j][0] *= al0; O[j][1] *= al0; O[j][2] *= al1; O[j][3] *= al1;
        }
#pragma unroll
        for (int j = 0; j < 8; j++) {
            Ps[(wrow + r0) * 33 + j * 4 + kq]     = packbf(sc[j][0], sc[j][1]);
            Ps[(wrow + r0 + 8) * 33 + j * 4 + kq] = packbf(sc[j][2], sc[j][3]);
        }
        __syncwarp();
#pragma unroll
        for (int ks = 0; ks < 4; ks++) {
            int kb = ks * 8;
            unsigned a[4];
            a[0] = Ps[(wrow + r0) * 33 + kb + kq];
            a[1] = Ps[(wrow + r0 + 8) * 33 + kb + kq];
            a[2] = Ps[(wrow + r0) * 33 + kb + kq + 4];
            a[3] = Ps[(wrow + r0 + 8) * 33 + kb + kq + 4];
#pragma unroll
            for (int j = 0; j < 8; j++) {
                unsigned b[2] = { Vt[(j * 8 + r0) * 33 + kb + kq],
                                  Vt[(j * 8 + r0) * 33 + kb + kq + 4] };
                mma16(O[j], a, b);
            }
        }
        __syncwarp();
    }
    float il0 = 1.f / l0, il1 = 1.f / l1;
    __nv_bfloat16* op = g_a3v + (size_t)bh * 16384 + (size_t)rt * 64 * 64;
#pragma unroll
    for (int j = 0; j < 8; j++) {
        *(unsigned*)(op + (wrow + r0) * 64 + j * 8 + kq * 2)       = packbf(O[j][0] * il0, O[j][1] * il0);
        *(unsigned*)(op + (wrow + r0 + 8) * 64 + j * 8 + kq * 2)   = packbf(O[j][2] * il1, O[j][3] * il1);
    }
}

// ---------------- fused attn1 (bf16): outh = softmax(q @ kl^T) @ Wm ----------------
// grid (32, 32), 256 threads.
// smem u32: KLs[256*33]@0, Qs[128*33]@8448, Ps[128*33]@12672; Wt[64*129]@0 (aliased)
__global__ __launch_bounds__(256, 1) void k_attn1() {
    int bx = blockIdx.x, bh = blockIdx.y;
    extern __shared__ unsigned sm[];
    unsigned* KLs = sm;
    unsigned* Qs  = sm + 8448;
    unsigned* Ps  = sm + 12672;
    unsigned* Wt  = sm;
    const __nv_bfloat16* qp  = g_q + ((size_t)bh << 18) + (size_t)bx * 128 * 64;
    const __nv_bfloat16* klp = g_kl + (size_t)bh * 16384;
    const __nv_bfloat16* wp  = g_wm + (size_t)bh * 16384;
    int tid = threadIdx.x, lane = tid & 31, w = tid >> 5;
    int r0 = lane >> 2, kq = lane & 3;
    int wrow = w * 16;

    {
        int r = tid >> 1, h = tid & 1;
        const __nv_bfloat16* ap = qp + r * 64 + h * 32;
        unsigned* dst = &Qs[r * 33 + h * 16];
#pragma unroll
        for (int i = 0; i < 4; i++) {
            uint4 u = ((const uint4*)ap)[i];
            dst[i * 4] = u.x; dst[i * 4 + 1] = u.y; dst[i * 4 + 2] = u.z; dst[i * 4 + 3] = u.w;
        }
    }
    {
        int r = tid;
        const __nv_bfloat16* ap = klp + r * 64;
        unsigned* dst = &KLs[r * 33];
#pragma unroll
        for (int i = 0; i < 8; i++) {
            uint4 u = ((const uint4*)ap)[i];
            dst[i * 4] = u.x; dst[i * 4 + 1] = u.y; dst[i * 4 + 2] = u.z; dst[i * 4 + 3] = u.w;
        }
    }
    __syncthreads();

    float sc[32][4];
#pragma unroll
    for (int j = 0; j < 32; j++)
#pragma unroll
        for (int q = 0; q < 4; q++) sc[j][q] = 0.f;
#pragma unroll
    for (int ks = 0; ks < 4; ks++) {
        int kb = ks * 8;
        unsigned a[4];
        a[0] = Qs[(wrow + r0) * 33 + kb + kq];
        a[1] = Qs[(wrow + r0 + 8) * 33 + kb + kq];
        a[2] = Qs[(wrow + r0) * 33 + kb + kq + 4];
        a[3] = Qs[(wrow + r0 + 8) * 33 + kb + kq + 4];
#pragma unroll
        for (int j = 0; j < 32; j++) {
            unsigned b[2] = { KLs[(j * 8 + r0) * 33 + kb + kq],
                              KLs[(j * 8 + r0) * 33 + kb + kq + 4] };
            mma16(sc[j], a, b);
        }
    }
    float m0 = -1e30f, m1 = -1e30f;
#pragma unroll
    for (int j = 0; j < 32; j++) {
        m0 = fmaxf(m0, fmaxf(sc[j][0], sc[j][1]));
        m1 = fmaxf(m1, fmaxf(sc[j][2], sc[j][3]));
    }
    m0 = fmaxf(m0, __shfl_xor_sync(0xffffffffu, m0, 1));
    m0 = fmaxf(m0, __shfl_xor_sync(0xffffffffu, m0, 2));
    m1 = fmaxf(m1, __shfl_xor_sync(0xffffffffu, m1, 1));
    m1 = fmaxf(m1, __shfl_xor_sync(0xffffffffu, m1, 2));
    float l0 = 0.f, l1 = 0.f;
#pragma unroll
    for (int j = 0; j < 32; j++) {
        sc[j][0] = __expf(sc[j][0] - m0); sc[j][1] = __expf(sc[j][1] - m0);
        sc[j][2] = __expf(sc[j][2] - m1); sc[j][3] = __expf(sc[j][3] - m1);
        l0 += sc[j][0] + sc[j][1];
        l1 += sc[j][2] + sc[j][3];
    }
    l0 += __shfl_xor_sync(0xffffffffu, l0, 1); l0 += __shfl_xor_sync(0xffffffffu, l0, 2);
    l1 += __shfl_xor_sync(0xffffffffu, l1, 1); l1 += __shfl_xor_sync(0xffffffffu, l1, 2);

    __syncthreads();   // KLs/Qs dead; load Wt transposed into aliased region
#pragma unroll
    for (int it = 0; it < 4; it++) {
        int i = tid + it * 256;
        int mp = i >> 3, dg = i & 7;
        const __nv_bfloat16* ap = wp + (size_t)(2 * mp) * 64 + dg * 8;
        uint4 ua = *(const uint4*)ap;
        uint4 ub = *(const uint4*)(ap + 64);
        unsigned av[4] = {ua.x, ua.y, ua.z, ua.w};
        unsigned bv[4] = {ub.x, ub.y, ub.z, ub.w};
#pragma unroll
        for (int q2 = 0; q2 < 4; q2++) {
            int d0 = dg * 8 + q2 * 2;
            Wt[d0 * 129 + mp]       = __byte_perm(av[q2], bv[q2], 0x5410);
            Wt[(d0 + 1) * 129 + mp] = __byte_perm(av[q2], bv[q2], 0x7632);
        }
    }
    __syncthreads();

    float O[8][4];
#pragma unroll
    for (int j = 0; j < 8; j++)
#pragma unroll
        for (int q = 0; q < 4; q++) O[j][q] = 0.f;

#pragma unroll
    for (int ch = 0; ch < 4; ch++) {
#pragma unroll
        for (int jj = 0; jj < 8; jj++) {
            int j = ch * 8 + jj;
            Ps[(wrow + r0) * 33 + jj * 4 + kq]     = packbf(sc[j][0], sc[j][1]);
            Ps[(wrow + r0 + 8) * 33 + jj * 4 + kq] = packbf(sc[j][2], sc[j][3]);
        }
        __syncwarp();
#pragma unroll
        for (int ks = 0; ks < 4; ks++) {
            int kb = ks * 8;
            unsigned a[4];
            a[0] = Ps[(wrow + r0) * 33 + kb + kq];
            a[1] = Ps[(wrow + r0 + 8) * 33 + kb + kq];
            a[2] = Ps[(wrow + r0) * 33 + kb + kq + 4];
            a[3] = Ps[(wrow + r0 + 8) * 33 + kb + kq + 4];
#pragma unroll
            for (int j = 0; j < 8; j++) {
                unsigned b[2] = { Wt[(j * 8 + r0) * 129 + ch * 32 + kb + kq],
                                  Wt[(j * 8 + r0) * 129 + ch * 32 + kb + kq + 4] };
                mma16(O[j], a, b);
            }
        }
        __syncwarp();
    }

    float il0 = 1.f / l0, il1 = 1.f / l1;
    __nv_bfloat16* op = g_outh + ((size_t)bh << 18) + (size_t)bx * 128 * 64;
#pragma unroll
    for (int j = 0; j < 8; j++) {
        *(unsigned*)(op + (wrow + r0) * 64 + j * 8 + kq * 2)     = packbf(O[j][0] * il0, O[j][1] * il0);
        *(unsigned*)(op + (wrow + r0 + 8) * 64 + j * 8 + kq * 2) = packbf(O[j][2] * il1, O[j][3] * il1);
    }
}

// ---------------- host orchestration ----------------
extern "C" void kernel_launch(void* const* d_in, const int* in_sizes, int n_in,
                              void* d_out, int out_size) {
    const float* x      = (const float*)d_in[0];
    const float* gamma  = (const float*)d_in[1];
    const float* beta   = (const float*)d_in[2];
    const float* w_qkv  = (const float*)d_in[3];
    const float* w_out  = (const float*)d_in[4];
    const float* b_out  = (const float*)d_in[5];
    const float* conv_w = (const float*)d_in[6];
    float* out = (float*)d_out;

    void* tp;
    cudaGetSymbolAddress(&tp, g_ql);   __nv_bfloat16* p_ql  = (__nv_bfloat16*)tp;
    cudaGetSymbolAddress(&tp, g_kl);   __nv_bfloat16* p_kl  = (__nv_bfloat16*)tp;
    cudaGetSymbolAddress(&tp, g_a2f);  float*         p_a2f = (float*)tp;
    cudaGetSymbolAddress(&tp, g_a2h);  __nv_bfloat16* p_a2h = (__nv_bfloat16*)tp;
    cudaGetSymbolAddress(&tp, g_z);    __nv_bfloat16* p_z   = (__nv_bfloat16*)tp;
    cudaGetSymbolAddress(&tp, g_zn);   __nv_bfloat16* p_zn  = (__nv_bfloat16*)tp;
    cudaGetSymbolAddress(&tp, g_az);   __nv_bfloat16* p_az  = (__nv_bfloat16*)tp;
    cudaGetSymbolAddress(&tp, g_w1);   __nv_bfloat16* p_w1  = (__nv_bfloat16*)tp;
    cudaGetSymbolAddress(&tp, g_w2);   __nv_bfloat16* p_w2  = (__nv_bfloat16*)tp;
    cudaGetSymbolAddress(&tp, g_a3v);  __nv_bfloat16* p_a3v = (__nv_bfloat16*)tp;
    cudaGetSymbolAddress(&tp, g_wm);   __nv_bfloat16* p_wm  = (__nv_bfloat16*)tp;

    cudaFuncSetAttribute(k_flash, cudaFuncAttributeMaxDynamicSharedMemorySize, 33792);
    cudaFuncSetAttribute(k_attn1, cudaFuncAttributeMaxDynamicSharedMemorySize, 67584);

    k_init<<<1, 1>>>();
    k_lnstats<<<Bb * Nn, 256>>>(x);

    // qkv = LN(x) @ w_qkv -> scatter bf16 q/k/v
    tgemm<<<dim3(24, 128, 1), 256>>>(x, w_qkv, nullptr, 512, 512, 1536, 0,
        0, 0, 0, 1, 0, 1, 1.f, 0.f, nullptr, nullptr, nullptr, gamma, beta);

    k_land<<<(2 * BHc * Mm * 32) / 256, 256>>>();

    // a2f = ql @ kl^T (fp32 out), then softmax fp32
    tgemm<<<dim3(4, 2, 32), 256>>>(p_ql, p_kl, p_a2f, 64, 64, 64, 256,
        (long)Mm * Dd, (long)Mm * Dd, (long)Mm * Mm, 0, 2, 2, 1.f, 0.f,
        nullptr, nullptr, nullptr, nullptr, nullptr);
    k_softmax1<<<BHc * Mm, 256>>>(p_a2f);

    k_sums<<<BHc, 256>>>(p_a2f);
    k_z0<<<(BHc * Mm * Mm / 2) / 256, 256>>>();

    // flash attn3 @ v
    k_flash<<<dim3(4, 32), 128, 33792>>>();

    // Newton-Schulz (bf16)
    __nv_bfloat16* zc = p_z; __nv_bfloat16* zo = p_zn;
    long sq = (long)Mm * Mm;
    for (int it = 0; it < 6; it++) {
        tgemm<<<dim3(4, 2, 32), 256>>>(p_a2h, zc, p_az, 256, 256, 256, 256,
            sq, sq, sq, 0, 1, 0, 1.f, 0.f, nullptr, nullptr, nullptr, nullptr, nullptr);
        tgemm<<<dim3(4, 2, 32), 256>>>(p_az, p_az, p_w1, 256, 256, 256, 256,
            sq, sq, sq, 0, 1, 0, -1.f, 7.f, p_az, nullptr, nullptr, nullptr, nullptr);
        tgemm<<<dim3(4, 2, 32), 256>>>(p_az, p_w1, p_w2, 256, 256, 256, 256,
            sq, sq, sq, 0, 1, 0, -1.f, 15.f, p_az, nullptr, nullptr, nullptr, nullptr);
        tgemm<<<dim3(4, 2, 32), 256>>>(zc, p_w2, zo, 256, 256, 256, 256,
            sq, sq, sq, 0, 1, 0, -0.25f, 3.25f, zc, nullptr, nullptr, nullptr, nullptr);
        __nv_bfloat16* t = zc; zc = zo; zo = t;
    }

    // wm = Z @ a3v
    tgemm<<<dim3(1, 2, 32), 256>>>(zc, p_a3v, p_wm, 256, 256, 64, 64,
        sq, (long)Mm * Dd, (long)Mm * Dd, 0, 1, 0, 1.f, 0.f,
        nullptr, nullptr, nullptr, nullptr, nullptr);

    // fused attn1 -> outh (bf16)
    k_attn1<<<dim3(32, 32), 256, 67584>>>();

    // conv residual add (bf16 RMW)
    k_conv2<<<dim3(32, 32), 256>>>(conv_w);

    // final: out = merge(outh) @ w_out + b_out + x
    tgemm<<<dim3(8, 128, 1), 256>>>(nullptr, w_out, out, 512, 512, 512, 512,
        0, 0, 0, 2, 0, 2, 1.f, 0.f, nullptr, b_out, x, nullptr, nullptr);
}

// round 5
// speedup vs baseline: 1.6910x; 1.6910x over previous
#include <cuda_runtime.h>
#include <cuda_bf16.h>
#include <cstddef>

#define Bb 4
#define Nn 4096
#define DIMV 512
#define Hh 8
#define Dd 64
#define Mm 256
#define BHc 32
#define QSCALE 0.125f

// ---------------- scratch (bf16 where possible) ----------------
__device__ __nv_bfloat16 g_q   [BHc*Nn*Dd];
__device__ __nv_bfloat16 g_k   [BHc*Nn*Dd];
__device__ __nv_bfloat16 g_v   [BHc*Nn*Dd];
__device__ __nv_bfloat16 g_ql  [BHc*Mm*Dd];
__device__ __nv_bfloat16 g_kl  [BHc*Mm*Dd];
__device__ float         g_a2f [BHc*Mm*Mm];   // fp32 scores / softmaxed a2
__device__ __nv_bfloat16 g_a2h [BHc*Mm*Mm];
__device__ __nv_bfloat16 g_z   [BHc*Mm*Mm];
__device__ __nv_bfloat16 g_zn  [BHc*Mm*Mm];
__device__ __nv_bfloat16 g_az  [BHc*Mm*Mm];
__device__ __nv_bfloat16 g_w1  [BHc*Mm*Mm];
__device__ __nv_bfloat16 g_w2  [BHc*Mm*Mm];
__device__ __nv_bfloat16 g_a3v [BHc*Mm*Dd];
__device__ __nv_bfloat16 g_wm  [BHc*Mm*Dd];
__device__ __nv_bfloat16 g_outh[BHc*Nn*Dd];
__device__ float g_mu[Bb*Nn];
__device__ float g_rs[Bb*Nn];
__device__ float g_ms1, g_ms2;

__device__ __forceinline__ unsigned packbf(float a, float b) {
    __nv_bfloat162 t = __floats2bfloat162_rn(a, b);
    return *reinterpret_cast<unsigned*>(&t);
}
__device__ __forceinline__ float2 unpackbf(unsigned u) {
    __nv_bfloat162 t = *reinterpret_cast<__nv_bfloat162*>(&u);
    return make_float2(__bfloat162float(t.x), __bfloat162float(t.y));
}
__device__ __forceinline__ void mma16(float* c, const unsigned* a, const unsigned* b) {
    asm volatile("mma.sync.aligned.m16n8k16.row.col.f32.bf16.bf16.f32 "
                 "{%0,%1,%2,%3},{%4,%5,%6,%7},{%8,%9},{%0,%1,%2,%3};"
                 : "+f"(c[0]), "+f"(c[1]), "+f"(c[2]), "+f"(c[3])
                 : "r"(a[0]), "r"(a[1]), "r"(a[2]), "r"(a[3]), "r"(b[0]), "r"(b[1]));
}

// ---------------- small kernels ----------------
__global__ void k_init() { g_ms1 = 0.f; g_ms2 = 0.f; }

__global__ void k_lnstats(const float* __restrict__ x) {
    int r = blockIdx.x, t = threadIdx.x;
    const float* xp = x + (size_t)r * DIMV;
    float v0 = xp[t], v1 = xp[t + 256];
    __shared__ float red[256];
    red[t] = v0 + v1; __syncthreads();
    for (int s = 128; s; s >>= 1) { if (t < s) red[t] += red[t + s]; __syncthreads(); }
    float mean = red[0] * (1.f / 512.f);
    __syncthreads();
    float d0 = v0 - mean, d1 = v1 - mean;
    red[t] = d0 * d0 + d1 * d1; __syncthreads();
    for (int s = 128; s; s >>= 1) { if (t < s) red[t] += red[t + s]; __syncthreads(); }
    if (t == 0) { g_mu[r] = mean; g_rs[r] = rsqrtf(red[0] * (1.f / 512.f) + 1e-5f); }
}

__global__ void k_land() {
    int idx = blockIdx.x * 256 + threadIdx.x;    // < 2*32*256*32
    int sel = idx >= (BHc * Mm * 32);
    int e = idx & (BHc * Mm * 32 - 1);
    int bh = e >> 13, j = (e >> 5) & 255, dp = e & 31;
    const __nv_bfloat16* src = sel ? g_k : g_q;
    const __nv_bfloat16* p = src + ((size_t)bh * 4096 + j * 16) * 64 + dp * 2;
    float s0 = 0.f, s1 = 0.f;
#pragma unroll
    for (int t = 0; t < 16; t++) {
        float2 f = unpackbf(*(const unsigned*)(p + t * 64));
        s0 += f.x; s1 += f.y;
    }
    __nv_bfloat16* dst = sel ? g_kl : g_ql;
    *(unsigned*)(dst + (size_t)bh * 16384 + j * 64 + dp * 2) =
        packbf(s0 * (1.f / 16.f), s1 * (1.f / 16.f));
}

__global__ void k_softmax1(float* __restrict__ p) {
    int row = blockIdx.x, t = threadIdx.x;
    p += (size_t)row * 256;
    float rv = p[t];
    __shared__ float red[256];
    red[t] = rv; __syncthreads();
    for (int s = 128; s; s >>= 1) { if (t < s) red[t] = fmaxf(red[t], red[t + s]); __syncthreads(); }
    float m = red[0]; __syncthreads();
    rv = __expf(rv - m);
    red[t] = rv; __syncthreads();
    for (int s = 128; s; s >>= 1) { if (t < s) red[t] += red[t + s]; __syncthreads(); }
    p[t] = rv / red[0];
}

__global__ void k_sums(const float* __restrict__ a) {
    int mat = blockIdx.x, t = threadIdx.x;
    const float* A = a + (size_t)mat * 65536;
    float cs = 0.f, rs = 0.f;
    for (int i = 0; i < 256; i++) { cs += A[i * 256 + t]; rs += A[t * 256 + i]; }
    __shared__ float red[256];
    red[t] = rs; __syncthreads();
    for (int s = 128; s; s >>= 1) { if (t < s) red[t] = fmaxf(red[t], red[t + s]); __syncthreads(); }
    if (!t) atomicMax((int*)&g_ms1, __float_as_int(red[0]));
    __syncthreads();
    red[t] = cs; __syncthreads();
    for (int s = 128; s; s >>= 1) { if (t < s) red[t] = fmaxf(red[t], red[t + s]); __syncthreads(); }
    if (!t) atomicMax((int*)&g_ms2, __float_as_int(red[0]));
}

__global__ void k_z0() {
    int p = blockIdx.x * 256 + threadIdx.x;      // pair index < 32*32768
    float inv = 1.f / (g_ms1 * g_ms2);
    int mat = p >> 15, rem = p & 32767;
    int r = rem >> 7, cp = (rem & 127) * 2;
    const float* A = g_a2f + ((size_t)mat << 16);
    float t0 = A[(size_t)cp * 256 + r], t1 = A[(size_t)(cp + 1) * 256 + r];
    *(unsigned*)(g_z + ((size_t)mat << 16) + (size_t)r * 256 + cp) = packbf(t0 * inv, t1 * inv);
    float2 s = *(const float2*)(A + (size_t)r * 256 + cp);
    *(unsigned*)(g_a2h + ((size_t)mat << 16) + (size_t)r * 256 + cp) = packbf(s.x, s.y);
}

__global__ void k_conv2(const float* __restrict__ w) {
    int nt = blockIdx.x, bh = blockIdx.y;
    __shared__ float vs[160][64];
    const __nv_bfloat16* vp = g_v + ((size_t)bh << 18);
    int n0 = nt * 128;
    for (int i = threadIdx.x; i < 160 * 8; i += 256) {
        int r = i >> 3, g = i & 7;
        int n = n0 - 16 + r;
        if (n >= 0 && n < 4096) {
            uint4 u = *(const uint4*)(vp + (size_t)n * 64 + g * 8);
            float2 f0 = unpackbf(u.x), f1 = unpackbf(u.y), f2 = unpackbf(u.z), f3 = unpackbf(u.w);
            vs[r][g * 8 + 0] = f0.x; vs[r][g * 8 + 1] = f0.y;
            vs[r][g * 8 + 2] = f1.x; vs[r][g * 8 + 3] = f1.y;
            vs[r][g * 8 + 4] = f2.x; vs[r][g * 8 + 5] = f2.y;
            vs[r][g * 8 + 6] = f3.x; vs[r][g * 8 + 7] = f3.y;
        } else {
#pragma unroll
            for (int q = 0; q < 8; q++) vs[r][g * 8 + q] = 0.f;
        }
    }
    __syncthreads();
    int h = bh & 7;
    float wr[33];
#pragma unroll
    for (int t = 0; t < 33; t++) wr[t] = w[h * 33 + t];
    int dp = threadIdx.x & 31, nl = threadIdx.x >> 5;
    for (int p = 0; p < 16; p++) {
        int n = nl + p * 8;
        float a0 = 0.f, a1 = 0.f;
#pragma unroll
        for (int t = 0; t < 33; t++) {
            a0 += wr[t] * vs[n + t][dp * 2];
            a1 += wr[t] * vs[n + t][dp * 2 + 1];
        }
        unsigned* op = (unsigned*)(g_outh + ((size_t)bh * 4096 + n0 + n) * 64 + dp * 2);
        float2 o = unpackbf(*op);
        *op = packbf(o.x + a0, o.y + a1);
    }
}

// ---------------- bf16 tensor-core batched GEMM ----------------
// tile 128x64, K-tile 32, 8 warps; smem holds packed bf16 pairs along K.
// Strides 20 u32 -> conflict-free fragment loads (r0*20 mod 32 multiples of 4).
__global__ __launch_bounds__(256) void tgemm(
    const void* Av, const void* Bv, void* Cv, int Kr,
    int lda, int ldb, int ldc, long sA, long sB, long sC,
    int aMode, int bMode, int outMode,
    float cM, float cA, const __nv_bfloat16* __restrict__ AE,
    const float* __restrict__ bias, const float* __restrict__ resid,
    const float* __restrict__ gammaP, const float* __restrict__ betaP) {
    int bz = blockIdx.z;
    const __nv_bfloat16* Ab = (const __nv_bfloat16*)Av + (size_t)bz * sA;
    const float*         Af = (const float*)Av + (size_t)bz * sA;
    const __nv_bfloat16* Bh = (const __nv_bfloat16*)Bv + (size_t)bz * sB;
    const float*         Bf = (const float*)Bv + (size_t)bz * sB;
    __nv_bfloat16*       Cb = (__nv_bfloat16*)Cv + (size_t)bz * sC;
    float*               Cf = (float*)Cv + (size_t)bz * sC;

    __shared__ unsigned As[128][20];
    __shared__ unsigned Bs[64][20];

    int tid = threadIdx.x, lane = tid & 31, w = tid >> 5;
    int wr = w >> 1, wc = w & 1;
    int rowBase = blockIdx.y * 128, colBase = blockIdx.x * 64;
    int r0 = lane >> 2, kq = lane & 3;

    float acc[2][4][4];
#pragma unroll
    for (int mi = 0; mi < 2; mi++)
#pragma unroll
        for (int ni = 0; ni < 4; ni++)
#pragma unroll
            for (int q = 0; q < 4; q++) acc[mi][ni][q] = 0.f;

    for (int k0 = 0; k0 < Kr; k0 += 32) {
        // ---- A tile (128 x 32 -> 16 pairs) ----
        {
            int r = tid >> 1, h = tid & 1;
            unsigned* dst = &As[r][h * 8];
            if (aMode == 0) {
                const __nv_bfloat16* ap = Ab + (size_t)(rowBase + r) * lda + k0 + h * 16;
                uint4 u0 = *(const uint4*)ap;
                uint4 u1 = *(const uint4*)(ap + 8);
                *(uint4*)&dst[0] = u0;
                *(uint4*)&dst[4] = u1;
            } else if (aMode == 1) {
                int gr = rowBase + r;
                float mu = g_mu[gr], rsd = g_rs[gr];
                const float* ap = Af + (size_t)gr * lda + k0 + h * 16;
                const float* gp = gammaP + k0 + h * 16;
                const float* bp = betaP + k0 + h * 16;
#pragma unroll
                for (int i = 0; i < 4; i++) {
                    float4 a4 = ((const float4*)ap)[i];
                    float4 g4 = ((const float4*)gp)[i];
                    float4 b4 = ((const float4*)bp)[i];
                    float n0 = (a4.x - mu) * rsd * g4.x + b4.x;
                    float n1 = (a4.y - mu) * rsd * g4.y + b4.y;
                    float n2 = (a4.z - mu) * rsd * g4.z + b4.z;
                    float n3 = (a4.w - mu) * rsd * g4.w + b4.w;
                    dst[i * 2]     = packbf(n0, n1);
                    dst[i * 2 + 1] = packbf(n2, n3);
                }
            } else {
                int gr = rowBase + r;
                int b = gr >> 12, n = gr & 4095;
                int kk = k0 + h * 16;
                int hh = kk >> 6, d = kk & 63;
                const __nv_bfloat16* ap = g_outh + (((size_t)(b * 8 + hh)) * 4096 + n) * 64 + d;
                uint4 u0 = *(const uint4*)ap;
                uint4 u1 = *(const uint4*)(ap + 8);
                *(uint4*)&dst[0] = u0;
                *(uint4*)&dst[4] = u1;
            }
        }
        // ---- B tile (32k x 64n -> Bs[n][kpair]) ----
        if (bMode == 2) {
            int n = tid >> 2, q = tid & 3;
            const __nv_bfloat16* bp = Bh + (size_t)(colBase + n) * ldb + k0 + q * 8;
            uint4 u = *(const uint4*)bp;
            *(uint4*)&Bs[n][q * 4] = u;
        } else if (bMode == 0) {
            int kp = tid >> 4, n0 = (tid & 15) * 4;
            const float* bp = Bf + (size_t)(k0 + 2 * kp) * ldb + colBase + n0;
            float4 r1 = *(const float4*)bp;
            float4 r2 = *(const float4*)(bp + ldb);
            Bs[n0 + 0][kp] = packbf(r1.x, r2.x);
            Bs[n0 + 1][kp] = packbf(r1.y, r2.y);
            Bs[n0 + 2][kp] = packbf(r1.z, r2.z);
            Bs[n0 + 3][kp] = packbf(r1.w, r2.w);
        } else {
            int kp = tid >> 4, n0 = (tid & 15) * 4;
            const __nv_bfloat16* bp = Bh + (size_t)(k0 + 2 * kp) * ldb + colBase + n0;
            uint2 r1 = *(const uint2*)bp;
            uint2 r2 = *(const uint2*)(bp + ldb);
            Bs[n0 + 0][kp] = __byte_perm(r1.x, r2.x, 0x5410);
            Bs[n0 + 1][kp] = __byte_perm(r1.x, r2.x, 0x7632);
            Bs[n0 + 2][kp] = __byte_perm(r1.y, r2.y, 0x5410);
            Bs[n0 + 3][kp] = __byte_perm(r1.y, r2.y, 0x7632);
        }
        __syncthreads();

#pragma unroll
        for (int ks = 0; ks < 2; ks++) {
            int kb = ks * 8;
            unsigned ar[2][4], br[4][2];
#pragma unroll
            for (int mi = 0; mi < 2; mi++) {
                int r = wr * 32 + mi * 16 + r0;
                ar[mi][0] = As[r][kb + kq];
                ar[mi][1] = As[r + 8][kb + kq];
                ar[mi][2] = As[r][kb + kq + 4];
                ar[mi][3] = As[r + 8][kb + kq + 4];
            }
#pragma unroll
            for (int ni = 0; ni < 4; ni++) {
                int n = wc * 32 + ni * 8 + r0;
                br[ni][0] = Bs[n][kb + kq];
                br[ni][1] = Bs[n][kb + kq + 4];
            }
#pragma unroll
            for (int mi = 0; mi < 2; mi++)
#pragma unroll
                for (int ni = 0; ni < 4; ni++) mma16(acc[mi][ni], ar[mi], br[ni]);
        }
        __syncthreads();
    }

    // ---- epilogue ----
#pragma unroll
    for (int mi = 0; mi < 2; mi++) {
#pragma unroll
        for (int ni = 0; ni < 4; ni++) {
            int rr = rowBase + wr * 32 + mi * 16 + r0;
            int cc = colBase + wc * 32 + ni * 8 + kq * 2;
#pragma unroll
            for (int hf = 0; hf < 2; hf++) {
                int r = rr + hf * 8;
                float v0 = cM * acc[mi][ni][hf * 2];
                float v1 = cM * acc[mi][ni][hf * 2 + 1];
                if (outMode == 0) {
                    if (AE) {
                        unsigned ae = *(const unsigned*)(AE + (size_t)bz * sA + (size_t)r * lda + cc);
                        float2 f = unpackbf(ae);
                        v0 += cA * f.x; v1 += cA * f.y;
                    }
                    *(unsigned*)(Cb + (size_t)r * ldc + cc) = packbf(v0, v1);
                } else if (outMode == 1) {
                    int which = cc >> 9, inner = cc & 511;
                    int hh = inner >> 6, d = inner & 63;
                    int b = r >> 12, n = r & 4095;
                    size_t dst = (((size_t)(b * 8 + hh)) * 4096 + n) * 64 + d;
                    if (which == 0)      *(unsigned*)(g_q + dst) = packbf(v0 * QSCALE, v1 * QSCALE);
                    else if (which == 1) *(unsigned*)(g_k + dst) = packbf(v0, v1);
                    else                 *(unsigned*)(g_v + dst) = packbf(v0, v1);
                } else {
                    if (bias) { v0 += bias[cc]; v1 += bias[cc + 1]; }
                    if (resid) {
                        float2 rx = *(const float2*)(resid + (size_t)r * ldc + cc);
                        v0 += rx.x; v1 += rx.y;
                    }
                    *(float2*)(Cf + (size_t)r * ldc + cc) = make_float2(v0, v1);
                }
            }
        }
    }
}

// ---------------- flash-style attn3 @ v (bf16) ----------------
// grid (4, 32), 128 threads; smem u32 stride 36: Qs Ks Vt Ps each 64*36=2304
__global__ __launch_bounds__(128) void k_flash() {
    int rt = blockIdx.x, bh = blockIdx.y;
    extern __shared__ unsigned sm[];
    unsigned* Qs = sm;
    unsigned* Ks = sm + 2304;
    unsigned* Vt = sm + 4608;
    unsigned* Ps = sm + 6912;
    const __nv_bfloat16* qlp = g_ql + (size_t)bh * 16384 + (size_t)rt * 64 * 64;
    const __nv_bfloat16* kp  = g_k + ((size_t)bh << 18);
    const __nv_bfloat16* vp  = g_v + ((size_t)bh << 18);
    int tid = threadIdx.x, lane = tid & 31, w = tid >> 5;
    int r0 = lane >> 2, kq = lane & 3;
    int wrow = w * 16;

    {
        int r = tid >> 1, h = tid & 1;
        const __nv_bfloat16* ap = qlp + r * 64 + h * 32;
        unsigned* dst = &Qs[r * 36 + h * 16];
#pragma unroll
        for (int i = 0; i < 4; i++) {
            uint4 u = ((const uint4*)ap)[i];
            *(uint4*)&dst[i * 4] = u;
        }
    }

    float O[8][4];
#pragma unroll
    for (int j = 0; j < 8; j++)
#pragma unroll
        for (int q = 0; q < 4; q++) O[j][q] = 0.f;
    float m0 = -1e30f, m1 = -1e30f, l0 = 0.f, l1 = 0.f;

    for (int n0 = 0; n0 < 4096; n0 += 64) {
        __syncthreads();
        {
            int r = tid >> 1, h = tid & 1;
            const __nv_bfloat16* ap = kp + (size_t)(n0 + r) * 64 + h * 32;
            unsigned* dst = &Ks[r * 36 + h * 16];
#pragma unroll
            for (int i = 0; i < 4; i++) {
                uint4 u = ((const uint4*)ap)[i];
                *(uint4*)&dst[i * 4] = u;
            }
        }
#pragma unroll
        for (int it = 0; it < 2; it++) {
            int i = tid + it * 128;
            int sp = i >> 3, dg = i & 7;
            const __nv_bfloat16* ap = vp + (size_t)(n0 + 2 * sp) * 64 + dg * 8;
            uint4 ua = *(const uint4*)ap;
            uint4 ub = *(const uint4*)(ap + 64);
            unsigned av[4] = {ua.x, ua.y, ua.z, ua.w};
            unsigned bv[4] = {ub.x, ub.y, ub.z, ub.w};
#pragma unroll
            for (int q2 = 0; q2 < 4; q2++) {
                int d0 = dg * 8 + q2 * 2;
                Vt[d0 * 36 + sp]       = __byte_perm(av[q2], bv[q2], 0x5410);
                Vt[(d0 + 1) * 36 + sp] = __byte_perm(av[q2], bv[q2], 0x7632);
            }
        }
        __syncthreads();

        float sc[8][4];
#pragma unroll
        for (int j = 0; j < 8; j++)
#pragma unroll
            for (int q = 0; q < 4; q++) sc[j][q] = 0.f;
#pragma unroll
        for (int ks = 0; ks < 4; ks++) {
            int kb = ks * 8;
            unsigned a[4];
            a[0] = Qs[(wrow + r0) * 36 + kb + kq];
            a[1] = Qs[(wrow + r0 + 8) * 36 + kb + kq];
            a[2] = Qs[(wrow + r0) * 36 + kb + kq + 4];
            a[3] = Qs[(wrow + r0 + 8) * 36 + kb + kq + 4];
#pragma unroll
            for (int j = 0; j < 8; j++) {
                unsigned b[2] = { Ks[(j * 8 + r0) * 36 + kb + kq],
                                  Ks[(j * 8 + r0) * 36 + kb + kq + 4] };
                mma16(sc[j], a, b);
            }
        }
        float tm0 = -1e30f, tm1 = -1e30f;
#pragma unroll
        for (int j = 0; j < 8; j++) {
            tm0 = fmaxf(tm0, fmaxf(sc[j][0], sc[j][1]));
            tm1 = fmaxf(tm1, fmaxf(sc[j][2], sc[j][3]));
        }
        tm0 = fmaxf(tm0, __shfl_xor_sync(0xffffffffu, tm0, 1));
        tm0 = fmaxf(tm0, __shfl_xor_sync(0xffffffffu, tm0, 2));
        tm1 = fmaxf(tm1, __shfl_xor_sync(0xffffffffu, tm1, 1));
        tm1 = fmaxf(tm1, __shfl_xor_sync(0xffffffffu, tm1, 2));
        float mn0 = fmaxf(m0, tm0), mn1 = fmaxf(m1, tm1);
        float al0 = __expf(m0 - mn0), al1 = __expf(m1 - mn1);
        float ts0 = 0.f, ts1 = 0.f;
#pragma unroll
        for (int j = 0; j < 8; j++) {
            sc[j][0] = __expf(sc[j][0] - mn0); sc[j][1] = __expf(sc[j][1] - mn0);
            sc[j][2] = __expf(sc[j][2] - mn1); sc[j][3] = __expf(sc[j][3] - mn1);
            ts0 += sc[j][0] + sc[j][1];
            ts1 += sc[j][2] + sc[j][3];
        }
        ts0 += __shfl_xor_sync(0xffffffffu, ts0, 1); ts0 += __shfl_xor_sync(0xffffffffu, ts0, 2);
        ts1 += __shfl_xor_sync(0xffffffffu, ts1, 1); ts1 += __shfl_xor_sync(0xffffffffu, ts1, 2);
        l0 = l0 * al0 + ts0; l1 = l1 * al1 + ts1;
        m0 = mn0; m1 = mn1;
#pragma unroll
        for (int j = 0; j < 8; j++) {
            O[j][0] *= al0; O[j][1] *= al0; O[j][2] *= al1; O[j][3] *= al1;
        }
#pragma unroll
        for (int j = 0; j < 8; j++) {
            Ps[(wrow + r0) * 36 + j * 4 + kq]     = packbf(sc[j][0], sc[j][1]);
            Ps[(wrow + r0 + 8) * 36 + j * 4 + kq] = packbf(sc[j][2], sc[j][3]);
        }
        __syncwarp();
#pragma unroll
        for (int ks = 0; ks < 4; ks++) {
            int kb = ks * 8;
            unsigned a[4];
            a[0] = Ps[(wrow + r0) * 36 + kb + kq];
            a[1] = Ps[(wrow + r0 + 8) * 36 + kb + kq];
            a[2] = Ps[(wrow + r0) * 36 + kb + kq + 4];
            a[3] = Ps[(wrow + r0 + 8) * 36 + kb + kq + 4];
#pragma unroll
            for (int j = 0; j < 8; j++) {
                unsigned b[2] = { Vt[(j * 8 + r0) * 36 + kb + kq],
                                  Vt[(j * 8 + r0) * 36 + kb + kq + 4] };
                mma16(O[j], a, b);
            }
        }
        __syncwarp();
    }
    float il0 = 1.f / l0, il1 = 1.f / l1;
    __nv_bfloat16* op = g_a3v + (size_t)bh * 16384 + (size_t)rt * 64 * 64;
#pragma unroll
    for (int j = 0; j < 8; j++) {
        *(unsigned*)(op + (wrow + r0) * 64 + j * 8 + kq * 2)       = packbf(O[j][0] * il0, O[j][1] * il0);
        *(unsigned*)(op + (wrow + r0 + 8) * 64 + j * 8 + kq * 2)   = packbf(O[j][2] * il1, O[j][3] * il1);
    }
}

// ---------------- fused attn1 (bf16): outh = softmax(q @ kl^T) @ Wm ----------------
// grid (32, 32), 256 threads; smem u32: KLs[256*36]@0, Qs[128*36]@9216,
// Ps[128*36]@13824; Wt[64*132]@0 (aliased over KLs)
__global__ __launch_bounds__(256, 1) void k_attn1() {
    int bx = blockIdx.x, bh = blockIdx.y;
    extern __shared__ unsigned sm[];
    unsigned* KLs = sm;
    unsigned* Qs  = sm + 9216;
    unsigned* Ps  = sm + 13824;
    unsigned* Wt  = sm;
    const __nv_bfloat16* qp  = g_q + ((size_t)bh << 18) + (size_t)bx * 128 * 64;
    const __nv_bfloat16* klp = g_kl + (size_t)bh * 16384;
    const __nv_bfloat16* wp  = g_wm + (size_t)bh * 16384;
    int tid = threadIdx.x, lane = tid & 31, w = tid >> 5;
    int r0 = lane >> 2, kq = lane & 3;
    int wrow = w * 16;

    {
        int r = tid >> 1, h = tid & 1;
        const __nv_bfloat16* ap = qp + r * 64 + h * 32;
        unsigned* dst = &Qs[r * 36 + h * 16];
#pragma unroll
        for (int i = 0; i < 4; i++) {
            uint4 u = ((const uint4*)ap)[i];
            *(uint4*)&dst[i * 4] = u;
        }
    }
    {
        int r = tid;
        const __nv_bfloat16* ap = klp + r * 64;
        unsigned* dst = &KLs[r * 36];
#pragma unroll
        for (int i = 0; i < 8; i++) {
            uint4 u = ((const uint4*)ap)[i];
            *(uint4*)&dst[i * 4] = u;
        }
    }
    __syncthreads();

    float sc[32][4];
#pragma unroll
    for (int j = 0; j < 32; j++)
#pragma unroll
        for (int q = 0; q < 4; q++) sc[j][q] = 0.f;
#pragma unroll
    for (int ks = 0; ks < 4; ks++) {
        int kb = ks * 8;
        unsigned a[4];
        a[0] = Qs[(wrow + r0) * 36 + kb + kq];
        a[1] = Qs[(wrow + r0 + 8) * 36 + kb + kq];
        a[2] = Qs[(wrow + r0) * 36 + kb + kq + 4];
        a[3] = Qs[(wrow + r0 + 8) * 36 + kb + kq + 4];
#pragma unroll
        for (int j = 0; j < 32; j++) {
            unsigned b[2] = { KLs[(j * 8 + r0) * 36 + kb + kq],
                              KLs[(j * 8 + r0) * 36 + kb + kq + 4] };
            mma16(sc[j], a, b);
        }
    }
    float m0 = -1e30f, m1 = -1e30f;
#pragma unroll
    for (int j = 0; j < 32; j++) {
        m0 = fmaxf(m0, fmaxf(sc[j][0], sc[j][1]));
        m1 = fmaxf(m1, fmaxf(sc[j][2], sc[j][3]));
    }
    m0 = fmaxf(m0, __shfl_xor_sync(0xffffffffu, m0, 1));
    m0 = fmaxf(m0, __shfl_xor_sync(0xffffffffu, m0, 2));
    m1 = fmaxf(m1, __shfl_xor_sync(0xffffffffu, m1, 1));
    m1 = fmaxf(m1, __shfl_xor_sync(0xffffffffu, m1, 2));
    float l0 = 0.f, l1 = 0.f;
#pragma unroll
    for (int j = 0; j < 32; j++) {
        sc[j][0] = __expf(sc[j][0] - m0); sc[j][1] = __expf(sc[j][1] - m0);
        sc[j][2] = __expf(sc[j][2] - m1); sc[j][3] = __expf(sc[j][3] - m1);
        l0 += sc[j][0] + sc[j][1];
        l1 += sc[j][2] + sc[j][3];
    }
    l0 += __shfl_xor_sync(0xffffffffu, l0, 1); l0 += __shfl_xor_sync(0xffffffffu, l0, 2);
    l1 += __shfl_xor_sync(0xffffffffu, l1, 1); l1 += __shfl_xor_sync(0xffffffffu, l1, 2);

    __syncthreads();   // KLs/Qs dead; load Wt transposed into aliased region
#pragma unroll
    for (int it = 0; it < 4; it++) {
        int i = tid + it * 256;
        int mp = i >> 3, dg = i & 7;
        const __nv_bfloat16* ap = wp + (size_t)(2 * mp) * 64 + dg * 8;
        uint4 ua = *(const uint4*)ap;
        uint4 ub = *(const uint4*)(ap + 64);
        unsigned av[4] = {ua.x, ua.y, ua.z, ua.w};
        unsigned bv[4] = {ub.x, ub.y, ub.z, ub.w};
#pragma unroll
        for (int q2 = 0; q2 < 4; q2++) {
            int d0 = dg * 8 + q2 * 2;
            Wt[d0 * 132 + mp]       = __byte_perm(av[q2], bv[q2], 0x5410);
            Wt[(d0 + 1) * 132 + mp] = __byte_perm(av[q2], bv[q2], 0x7632);
        }
    }
    __syncthreads();

    float O[8][4];
#pragma unroll
    for (int j = 0; j < 8; j++)
#pragma unroll
        for (int q = 0; q < 4; q++) O[j][q] = 0.f;

#pragma unroll
    for (int ch = 0; ch < 4; ch++) {
#pragma unroll
        for (int jj = 0; jj < 8; jj++) {
            int j = ch * 8 + jj;
            Ps[(wrow + r0) * 36 + jj * 4 + kq]     = packbf(sc[j][0], sc[j][1]);
            Ps[(wrow + r0 + 8) * 36 + jj * 4 + kq] = packbf(sc[j][2], sc[j][3]);
        }
        __syncwarp();
#pragma unroll
        for (int ks = 0; ks < 4; ks++) {
            int kb = ks * 8;
            unsigned a[4];
            a[0] = Ps[(wrow + r0) * 36 + kb + kq];
            a[1] = Ps[(wrow + r0 + 8) * 36 + kb + kq];
            a[2] = Ps[(wrow + r0) * 36 + kb + kq + 4];
            a[3] = Ps[(wrow + r0 + 8) * 36 + kb + kq + 4];
#pragma unroll
            for (int j = 0; j < 8; j++) {
                unsigned b[2] = { Wt[(j * 8 + r0) * 132 + ch * 32 + kb + kq],
                                  Wt[(j * 8 + r0) * 132 + ch * 32 + kb + kq + 4] };
                mma16(O[j], a, b);
            }
        }
        __syncwarp();
    }

    float il0 = 1.f / l0, il1 = 1.f / l1;
    __nv_bfloat16* op = g_outh + ((size_t)bh << 18) + (size_t)bx * 128 * 64;
#pragma unroll
    for (int j = 0; j < 8; j++) {
        *(unsigned*)(op + (wrow + r0) * 64 + j * 8 + kq * 2)     = packbf(O[j][0] * il0, O[j][1] * il0);
        *(unsigned*)(op + (wrow + r0 + 8) * 64 + j * 8 + kq * 2) = packbf(O[j][2] * il1, O[j][3] * il1);
    }
}

// ---------------- host orchestration ----------------
extern "C" void kernel_launch(void* const* d_in, const int* in_sizes, int n_in,
                              void* d_out, int out_size) {
    const float* x      = (const float*)d_in[0];
    const float* gamma  = (const float*)d_in[1];
    const float* beta   = (const float*)d_in[2];
    const float* w_qkv  = (const float*)d_in[3];
    const float* w_out  = (const float*)d_in[4];
    const float* b_out  = (const float*)d_in[5];
    const float* conv_w = (const float*)d_in[6];
    float* out = (float*)d_out;

    void* tp;
    cudaGetSymbolAddress(&tp, g_ql);   __nv_bfloat16* p_ql  = (__nv_bfloat16*)tp;
    cudaGetSymbolAddress(&tp, g_kl);   __nv_bfloat16* p_kl  = (__nv_bfloat16*)tp;
    cudaGetSymbolAddress(&tp, g_a2f);  float*         p_a2f = (float*)tp;
    cudaGetSymbolAddress(&tp, g_a2h);  __nv_bfloat16* p_a2h = (__nv_bfloat16*)tp;
    cudaGetSymbolAddress(&tp, g_z);    __nv_bfloat16* p_z   = (__nv_bfloat16*)tp;
    cudaGetSymbolAddress(&tp, g_zn);   __nv_bfloat16* p_zn  = (__nv_bfloat16*)tp;
    cudaGetSymbolAddress(&tp, g_az);   __nv_bfloat16* p_az  = (__nv_bfloat16*)tp;
    cudaGetSymbolAddress(&tp, g_w1);   __nv_bfloat16* p_w1  = (__nv_bfloat16*)tp;
    cudaGetSymbolAddress(&tp, g_w2);   __nv_bfloat16* p_w2  = (__nv_bfloat16*)tp;
    cudaGetSymbolAddress(&tp, g_a3v);  __nv_bfloat16* p_a3v = (__nv_bfloat16*)tp;
    cudaGetSymbolAddress(&tp, g_wm);   __nv_bfloat16* p_wm  = (__nv_bfloat16*)tp;

    cudaFuncSetAttribute(k_flash, cudaFuncAttributeMaxDynamicSharedMemorySize, 36864);
    cudaFuncSetAttribute(k_attn1, cudaFuncAttributeMaxDynamicSharedMemorySize, 73728);

    k_init<<<1, 1>>>();
    k_lnstats<<<Bb * Nn, 256>>>(x);

    // qkv = LN(x) @ w_qkv -> scatter bf16 q/k/v
    tgemm<<<dim3(24, 128, 1), 256>>>(x, w_qkv, nullptr, 512, 512, 1536, 0,
        0, 0, 0, 1, 0, 1, 1.f, 0.f, nullptr, nullptr, nullptr, gamma, beta);

    k_land<<<(2 * BHc * Mm * 32) / 256, 256>>>();

    // a2f = ql @ kl^T (fp32 out), then softmax fp32
    tgemm<<<dim3(4, 2, 32), 256>>>(p_ql, p_kl, p_a2f, 64, 64, 64, 256,
        (long)Mm * Dd, (long)Mm * Dd, (long)Mm * Mm, 0, 2, 2, 1.f, 0.f,
        nullptr, nullptr, nullptr, nullptr, nullptr);
    k_softmax1<<<BHc * Mm, 256>>>(p_a2f);

    k_sums<<<BHc, 256>>>(p_a2f);
    k_z0<<<(BHc * Mm * Mm / 2) / 256, 256>>>();

    // flash attn3 @ v
    k_flash<<<dim3(4, 32), 128, 36864>>>();

    // Newton-Schulz (bf16)
    __nv_bfloat16* zc = p_z; __nv_bfloat16* zo = p_zn;
    long sq = (long)Mm * Mm;
    for (int it = 0; it < 6; it++) {
        tgemm<<<dim3(4, 2, 32), 256>>>(p_a2h, zc, p_az, 256, 256, 256, 256,
            sq, sq, sq, 0, 1, 0, 1.f, 0.f, nullptr, nullptr, nullptr, nullptr, nullptr);
        tgemm<<<dim3(4, 2, 32), 256>>>(p_az, p_az, p_w1, 256, 256, 256, 256,
            sq, sq, sq, 0, 1, 0, -1.f, 7.f, p_az, nullptr, nullptr, nullptr, nullptr);
        tgemm<<<dim3(4, 2, 32), 256>>>(p_az, p_w1, p_w2, 256, 256, 256, 256,
            sq, sq, sq, 0, 1, 0, -1.f, 15.f, p_az, nullptr, nullptr, nullptr, nullptr);
        tgemm<<<dim3(4, 2, 32), 256>>>(zc, p_w2, zo, 256, 256, 256, 256,
            sq, sq, sq, 0, 1, 0, -0.25f, 3.25f, zc, nullptr, nullptr, nullptr, nullptr);
        __nv_bfloat16* t = zc; zc = zo; zo = t;
    }

    // wm = Z @ a3v
    tgemm<<<dim3(1, 2, 32), 256>>>(zc, p_a3v, p_wm, 256, 256, 64, 64,
        sq, (long)Mm * Dd, (long)Mm * Dd, 0, 1, 0, 1.f, 0.f,
        nullptr, nullptr, nullptr, nullptr, nullptr);

    // fused attn1 -> outh (bf16)
    k_attn1<<<dim3(32, 32), 256, 73728>>>();

    // conv residual add (bf16 RMW)
    k_conv2<<<dim3(32, 32), 256>>>(conv_w);

    // final: out = merge(outh) @ w_out + b_out + x
    tgemm<<<dim3(8, 128, 1), 256>>>(nullptr, w_out, out, 512, 512, 512, 512,
        0, 0, 0, 2, 0, 2, 1.f, 0.f, nullptr, b_out, x, nullptr, nullptr);
}

// round 6
// speedup vs baseline: 1.8011x; 1.0651x over previous
#include <cuda_runtime.h>
#include <cuda_bf16.h>
#include <cstddef>

#define Bb 4
#define Nn 4096
#define DIMV 512
#define Hh 8
#define Dd 64
#define Mm 256
#define BHc 32
#define QSCALE 0.125f

// ---------------- scratch ----------------
__device__ __nv_bfloat16 g_q   [BHc*Nn*Dd];
__device__ __nv_bfloat16 g_k   [BHc*Nn*Dd];
__device__ __nv_bfloat16 g_v   [BHc*Nn*Dd];
__device__ __nv_bfloat16 g_ql  [BHc*Mm*Dd];
__device__ __nv_bfloat16 g_kl  [BHc*Mm*Dd];
__device__ float         g_a2f [BHc*Mm*Mm];
__device__ __nv_bfloat16 g_a2h [BHc*Mm*Mm];
__device__ __nv_bfloat16 g_z   [BHc*Mm*Mm];
__device__ __nv_bfloat16 g_zn  [BHc*Mm*Mm];
__device__ __nv_bfloat16 g_az  [BHc*Mm*Mm];
__device__ __nv_bfloat16 g_w1  [BHc*Mm*Mm];
__device__ __nv_bfloat16 g_w2  [BHc*Mm*Mm];
__device__ __nv_bfloat16 g_a3v [BHc*Mm*Dd];
__device__ __nv_bfloat16 g_wm  [BHc*Mm*Dd];
__device__ __nv_bfloat16 g_outh[BHc*Nn*Dd];
__device__ float g_mu[Bb*Nn];
__device__ float g_rs[Bb*Nn];
__device__ float g_ms1, g_ms2;

__device__ __forceinline__ unsigned packbf(float a, float b) {
    __nv_bfloat162 t = __floats2bfloat162_rn(a, b);
    return *reinterpret_cast<unsigned*>(&t);
}
__device__ __forceinline__ float2 unpackbf(unsigned u) {
    __nv_bfloat162 t = *reinterpret_cast<__nv_bfloat162*>(&u);
    return make_float2(__bfloat162float(t.x), __bfloat162float(t.y));
}
__device__ __forceinline__ void mma16(float* c, const unsigned* a, const unsigned* b) {
    asm volatile("mma.sync.aligned.m16n8k16.row.col.f32.bf16.bf16.f32 "
                 "{%0,%1,%2,%3},{%4,%5,%6,%7},{%8,%9},{%0,%1,%2,%3};"
                 : "+f"(c[0]), "+f"(c[1]), "+f"(c[2]), "+f"(c[3])
                 : "r"(a[0]), "r"(a[1]), "r"(a[2]), "r"(a[3]), "r"(b[0]), "r"(b[1]));
}

// ---------------- small kernels ----------------
__global__ void k_lnstats(const float* __restrict__ x) {
    int r = blockIdx.x, t = threadIdx.x;
    if (r == 0 && t == 0) { g_ms1 = 0.f; g_ms2 = 0.f; }
    const float* xp = x + (size_t)r * DIMV;
    float v0 = xp[t], v1 = xp[t + 256];
    __shared__ float red[256];
    red[t] = v0 + v1; __syncthreads();
    for (int s = 128; s; s >>= 1) { if (t < s) red[t] += red[t + s]; __syncthreads(); }
    float mean = red[0] * (1.f / 512.f);
    __syncthreads();
    float d0 = v0 - mean, d1 = v1 - mean;
    red[t] = d0 * d0 + d1 * d1; __syncthreads();
    for (int s = 128; s; s >>= 1) { if (t < s) red[t] += red[t + s]; __syncthreads(); }
    if (t == 0) { g_mu[r] = mean; g_rs[r] = rsqrtf(red[0] * (1.f / 512.f) + 1e-5f); }
}

__global__ void k_land() {
    int idx = blockIdx.x * 256 + threadIdx.x;
    int sel = idx >= (BHc * Mm * 32);
    int e = idx & (BHc * Mm * 32 - 1);
    int bh = e >> 13, j = (e >> 5) & 255, dp = e & 31;
    const __nv_bfloat16* src = sel ? g_k : g_q;
    const __nv_bfloat16* p = src + ((size_t)bh * 4096 + j * 16) * 64 + dp * 2;
    float s0 = 0.f, s1 = 0.f;
#pragma unroll
    for (int t = 0; t < 16; t++) {
        float2 f = unpackbf(*(const unsigned*)(p + t * 64));
        s0 += f.x; s1 += f.y;
    }
    __nv_bfloat16* dst = sel ? g_kl : g_ql;
    *(unsigned*)(dst + (size_t)bh * 16384 + j * 64 + dp * 2) =
        packbf(s0 * (1.f / 16.f), s1 * (1.f / 16.f));
}

__global__ void k_softmax1(float* __restrict__ p) {
    int row = blockIdx.x, t = threadIdx.x;
    p += (size_t)row * 256;
    float rv = p[t];
    __shared__ float red[256];
    red[t] = rv; __syncthreads();
    for (int s = 128; s; s >>= 1) { if (t < s) red[t] = fmaxf(red[t], red[t + s]); __syncthreads(); }
    float m = red[0]; __syncthreads();
    rv = __expf(rv - m);
    red[t] = rv; __syncthreads();
    for (int s = 128; s; s >>= 1) { if (t < s) red[t] += red[t + s]; __syncthreads(); }
    p[t] = rv / red[0];
}

__global__ void k_sums(const float* __restrict__ a) {
    int mat = blockIdx.x, t = threadIdx.x;
    const float* A = a + (size_t)mat * 65536;
    float cs = 0.f, rs = 0.f;
    for (int i = 0; i < 256; i++) { cs += A[i * 256 + t]; rs += A[t * 256 + i]; }
    __shared__ float red[256];
    red[t] = rs; __syncthreads();
    for (int s = 128; s; s >>= 1) { if (t < s) red[t] = fmaxf(red[t], red[t + s]); __syncthreads(); }
    if (!t) atomicMax((int*)&g_ms1, __float_as_int(red[0]));
    __syncthreads();
    red[t] = cs; __syncthreads();
    for (int s = 128; s; s >>= 1) { if (t < s) red[t] = fmaxf(red[t], red[t + s]); __syncthreads(); }
    if (!t) atomicMax((int*)&g_ms2, __float_as_int(red[0]));
}

__global__ void k_z0() {
    int p = blockIdx.x * 256 + threadIdx.x;
    float inv = 1.f / (g_ms1 * g_ms2);
    int mat = p >> 15, rem = p & 32767;
    int r = rem >> 7, cp = (rem & 127) * 2;
    const float* A = g_a2f + ((size_t)mat << 16);
    float t0 = A[(size_t)cp * 256 + r], t1 = A[(size_t)(cp + 1) * 256 + r];
    *(unsigned*)(g_z + ((size_t)mat << 16) + (size_t)r * 256 + cp) = packbf(t0 * inv, t1 * inv);
    float2 s = *(const float2*)(A + (size_t)r * 256 + cp);
    *(unsigned*)(g_a2h + ((size_t)mat << 16) + (size_t)r * 256 + cp) = packbf(s.x, s.y);
}

__global__ void k_conv2(const float* __restrict__ w) {
    int nt = blockIdx.x, bh = blockIdx.y;
    __shared__ float vs[160][64];
    const __nv_bfloat16* vp = g_v + ((size_t)bh << 18);
    int n0 = nt * 128;
    for (int i = threadIdx.x; i < 160 * 8; i += 256) {
        int r = i >> 3, g = i & 7;
        int n = n0 - 16 + r;
        if (n >= 0 && n < 4096) {
            uint4 u = *(const uint4*)(vp + (size_t)n * 64 + g * 8);
            float2 f0 = unpackbf(u.x), f1 = unpackbf(u.y), f2 = unpackbf(u.z), f3 = unpackbf(u.w);
            vs[r][g * 8 + 0] = f0.x; vs[r][g * 8 + 1] = f0.y;
            vs[r][g * 8 + 2] = f1.x; vs[r][g * 8 + 3] = f1.y;
            vs[r][g * 8 + 4] = f2.x; vs[r][g * 8 + 5] = f2.y;
            vs[r][g * 8 + 6] = f3.x; vs[r][g * 8 + 7] = f3.y;
        } else {
#pragma unroll
            for (int q = 0; q < 8; q++) vs[r][g * 8 + q] = 0.f;
        }
    }
    __syncthreads();
    int h = bh & 7;
    float wr[33];
#pragma unroll
    for (int t = 0; t < 33; t++) wr[t] = w[h * 33 + t];
    int dp = threadIdx.x & 31, nl = threadIdx.x >> 5;
    for (int p = 0; p < 16; p++) {
        int n = nl + p * 8;
        float a0 = 0.f, a1 = 0.f;
#pragma unroll
        for (int t = 0; t < 33; t++) {
            a0 += wr[t] * vs[n + t][dp * 2];
            a1 += wr[t] * vs[n + t][dp * 2 + 1];
        }
        unsigned* op = (unsigned*)(g_outh + ((size_t)bh * 4096 + n0 + n) * 64 + dp * 2);
        float2 o = unpackbf(*op);
        *op = packbf(o.x + a0, o.y + a1);
    }
}

// ---------------- pipelined bf16 GEMM (tile 128x64, ping-pong smem) ----------------
// aMode: 0=bf16 rows, 1=fp32+LN(x), 2=outh head-merge
// bMode: 0=fp32 [k][n], 1=bf16 [k][n], 2=bf16 [n][k]
// outMode: 0=bf16 C (+cA*AE), 1=qkv split, 2=fp32 C (+bias,+resid)
__global__ __launch_bounds__(256) void tgemm(
    const void* Av, const void* Bv, void* Cv, int Kr,
    int lda, int ldb, int ldc, long sA, long sB, long sC,
    int aMode, int bMode, int outMode,
    float cM, float cA, const __nv_bfloat16* __restrict__ AE,
    const float* __restrict__ bias, const float* __restrict__ resid,
    const float* __restrict__ gammaP, const float* __restrict__ betaP) {
    int bz = blockIdx.z;
    const __nv_bfloat16* Ab = (const __nv_bfloat16*)Av + (size_t)bz * sA;
    const float*         Af = (const float*)Av + (size_t)bz * sA;
    const __nv_bfloat16* Bh = (const __nv_bfloat16*)Bv + (size_t)bz * sB;
    const float*         Bf = (const float*)Bv + (size_t)bz * sB;
    __nv_bfloat16*       Cb = (__nv_bfloat16*)Cv + (size_t)bz * sC;
    float*               Cf = (float*)Cv + (size_t)bz * sC;

    __shared__ unsigned As[2][128][20];
    __shared__ unsigned Bs[2][64][20];

    int tid = threadIdx.x, lane = tid & 31, w = tid >> 5;
    int wr = w >> 1, wc = w & 1;
    int rowBase = blockIdx.y * 128, colBase = blockIdx.x * 64;
    int r0 = lane >> 2, kq = lane & 3;
    int ar_ = tid >> 1, ah_ = tid & 1;
    int bn_ = tid >> 2, bq_ = tid & 3;
    int bkp = tid >> 4, bn0 = (tid & 15) * 4;

    float acc[2][4][4];
#pragma unroll
    for (int mi = 0; mi < 2; mi++)
#pragma unroll
        for (int ni = 0; ni < 4; ni++)
#pragma unroll
            for (int q = 0; q < 4; q++) acc[mi][ni][q] = 0.f;

    auto fetchA = [&](int kk, unsigned* pr) {
        if (aMode == 0) {
            const __nv_bfloat16* ap = Ab + (size_t)(rowBase + ar_) * lda + kk + ah_ * 16;
            *(uint4*)&pr[0] = *(const uint4*)ap;
            *(uint4*)&pr[4] = *(const uint4*)(ap + 8);
        } else if (aMode == 1) {
            const float* ap = Af + (size_t)(rowBase + ar_) * lda + kk + ah_ * 16;
            *(float4*)&pr[0]  = ((const float4*)ap)[0];
            *(float4*)&pr[4]  = ((const float4*)ap)[1];
            *(float4*)&pr[8]  = ((const float4*)ap)[2];
            *(float4*)&pr[12] = ((const float4*)ap)[3];
        } else {
            int gr = rowBase + ar_;
            int b = gr >> 12, n = gr & 4095;
            int kk2 = kk + ah_ * 16, hh = kk2 >> 6, d = kk2 & 63;
            const __nv_bfloat16* ap = g_outh + (((size_t)(b * 8 + hh)) * 4096 + n) * 64 + d;
            *(uint4*)&pr[0] = *(const uint4*)ap;
            *(uint4*)&pr[4] = *(const uint4*)(ap + 8);
        }
    };
    auto storeA = [&](int kk, const unsigned* pr, int bf) {
        unsigned* dst = &As[bf][ar_][ah_ * 8];
        if (aMode == 1) {
            float mu = g_mu[rowBase + ar_], rsd = g_rs[rowBase + ar_];
            const float* gp = gammaP + kk + ah_ * 16;
            const float* bp = betaP + kk + ah_ * 16;
#pragma unroll
            for (int i = 0; i < 4; i++) {
                float4 a4 = *(const float4*)&pr[i * 4];
                float4 g4 = ((const float4*)gp)[i];
                float4 b4 = ((const float4*)bp)[i];
                float n0v = (a4.x - mu) * rsd * g4.x + b4.x;
                float n1v = (a4.y - mu) * rsd * g4.y + b4.y;
                float n2v = (a4.z - mu) * rsd * g4.z + b4.z;
                float n3v = (a4.w - mu) * rsd * g4.w + b4.w;
                dst[i * 2]     = packbf(n0v, n1v);
                dst[i * 2 + 1] = packbf(n2v, n3v);
            }
        } else {
            *(uint4*)&dst[0] = *(const uint4*)&pr[0];
            *(uint4*)&dst[4] = *(const uint4*)&pr[4];
        }
    };
    auto fetchB = [&](int kk, unsigned* pr) {
        if (bMode == 2) {
            const __nv_bfloat16* bp = Bh + (size_t)(colBase + bn_) * ldb + kk + bq_ * 8;
            *(uint4*)&pr[0] = *(const uint4*)bp;
        } else if (bMode == 0) {
            const float* bp = Bf + (size_t)(kk + 2 * bkp) * ldb + colBase + bn0;
            *(float4*)&pr[0] = *(const float4*)bp;
            *(float4*)&pr[4] = *(const float4*)(bp + ldb);
        } else {
            const __nv_bfloat16* bp = Bh + (size_t)(kk + 2 * bkp) * ldb + colBase + bn0;
            *(uint2*)&pr[0] = *(const uint2*)bp;
            *(uint2*)&pr[2] = *(const uint2*)(bp + ldb);
        }
    };
    auto storeB = [&](const unsigned* pr, int bf) {
        if (bMode == 2) {
            *(uint4*)&Bs[bf][bn_][bq_ * 4] = *(const uint4*)&pr[0];
        } else if (bMode == 0) {
            float4 r1 = *(const float4*)&pr[0];
            float4 r2 = *(const float4*)&pr[4];
            Bs[bf][bn0 + 0][bkp] = packbf(r1.x, r2.x);
            Bs[bf][bn0 + 1][bkp] = packbf(r1.y, r2.y);
            Bs[bf][bn0 + 2][bkp] = packbf(r1.z, r2.z);
            Bs[bf][bn0 + 3][bkp] = packbf(r1.w, r2.w);
        } else {
            uint2 r1 = *(const uint2*)&pr[0];
            uint2 r2 = *(const uint2*)&pr[2];
            Bs[bf][bn0 + 0][bkp] = __byte_perm(r1.x, r2.x, 0x5410);
            Bs[bf][bn0 + 1][bkp] = __byte_perm(r1.x, r2.x, 0x7632);
            Bs[bf][bn0 + 2][bkp] = __byte_perm(r1.y, r2.y, 0x5410);
            Bs[bf][bn0 + 3][bkp] = __byte_perm(r1.y, r2.y, 0x7632);
        }
    };

    unsigned prA[16], prB[8];
    fetchA(0, prA); fetchB(0, prB);
    storeA(0, prA, 0); storeB(prB, 0);
    __syncthreads();

    int buf = 0;
    for (int k0 = 0; k0 < Kr; k0 += 32) {
        bool nxt = (k0 + 32) < Kr;
        if (nxt) { fetchA(k0 + 32, prA); fetchB(k0 + 32, prB); }
#pragma unroll
        for (int ks = 0; ks < 2; ks++) {
            int kb = ks * 8;
            unsigned arf[2][4], brf[4][2];
#pragma unroll
            for (int mi = 0; mi < 2; mi++) {
                int r = wr * 32 + mi * 16 + r0;
                arf[mi][0] = As[buf][r][kb + kq];
                arf[mi][1] = As[buf][r + 8][kb + kq];
                arf[mi][2] = As[buf][r][kb + kq + 4];
                arf[mi][3] = As[buf][r + 8][kb + kq + 4];
            }
#pragma unroll
            for (int ni = 0; ni < 4; ni++) {
                int n = wc * 32 + ni * 8 + r0;
                brf[ni][0] = Bs[buf][n][kb + kq];
                brf[ni][1] = Bs[buf][n][kb + kq + 4];
            }
#pragma unroll
            for (int mi = 0; mi < 2; mi++)
#pragma unroll
                for (int ni = 0; ni < 4; ni++) mma16(acc[mi][ni], arf[mi], brf[ni]);
        }
        if (nxt) { storeA(k0 + 32, prA, buf ^ 1); storeB(prB, buf ^ 1); }
        __syncthreads();
        buf ^= 1;
    }

    // ---- epilogue ----
#pragma unroll
    for (int mi = 0; mi < 2; mi++) {
#pragma unroll
        for (int ni = 0; ni < 4; ni++) {
            int rr = rowBase + wr * 32 + mi * 16 + r0;
            int cc = colBase + wc * 32 + ni * 8 + kq * 2;
#pragma unroll
            for (int hf = 0; hf < 2; hf++) {
                int r = rr + hf * 8;
                float v0 = cM * acc[mi][ni][hf * 2];
                float v1 = cM * acc[mi][ni][hf * 2 + 1];
                if (outMode == 0) {
                    if (AE) {
                        unsigned ae = *(const unsigned*)(AE + (size_t)bz * sA + (size_t)r * lda + cc);
                        float2 f = unpackbf(ae);
                        v0 += cA * f.x; v1 += cA * f.y;
                    }
                    *(unsigned*)(Cb + (size_t)r * ldc + cc) = packbf(v0, v1);
                } else if (outMode == 1) {
                    int which = cc >> 9, inner = cc & 511;
                    int hh = inner >> 6, d = inner & 63;
                    int b = r >> 12, n = r & 4095;
                    size_t dst = (((size_t)(b * 8 + hh)) * 4096 + n) * 64 + d;
                    if (which == 0)      *(unsigned*)(g_q + dst) = packbf(v0 * QSCALE, v1 * QSCALE);
                    else if (which == 1) *(unsigned*)(g_k + dst) = packbf(v0, v1);
                    else                 *(unsigned*)(g_v + dst) = packbf(v0, v1);
                } else {
                    if (bias) { v0 += bias[cc]; v1 += bias[cc + 1]; }
                    if (resid) {
                        float2 rx = *(const float2*)(resid + (size_t)r * ldc + cc);
                        v0 += rx.x; v1 += rx.y;
                    }
                    *(float2*)(Cf + (size_t)r * ldc + cc) = make_float2(v0, v1);
                }
            }
        }
    }
}

// ---------------- Newton-Schulz GEMM: 256x256x256 batched, tile 128x128 ----------------
// C = cM*(A@B) + cA*AE, all bf16 [256,256] row-major; grid (2,2,32) = one wave.
__global__ __launch_bounds__(256) void ngemm(
    const __nv_bfloat16* __restrict__ A, const __nv_bfloat16* __restrict__ B,
    __nv_bfloat16* __restrict__ C, float cM, float cA,
    const __nv_bfloat16* __restrict__ AE) {
    int bz = blockIdx.z;
    A += (size_t)bz << 16; B += (size_t)bz << 16; C += (size_t)bz << 16;
    const __nv_bfloat16* AEp = AE ? AE + ((size_t)bz << 16) : nullptr;

    __shared__ unsigned As[2][128][20];
    __shared__ unsigned Bs[2][128][20];

    int tid = threadIdx.x, lane = tid & 31, w = tid >> 5;
    int wr = w >> 2, wc = w & 3;
    int rowBase = blockIdx.y * 128, colBase = blockIdx.x * 128;
    int r0 = lane >> 2, kq = lane & 3;
    int ar_ = tid >> 1, ah_ = tid & 1;
    int bkp = tid >> 4, bn0 = (tid & 15) * 8;

    float acc[4][4][4];
#pragma unroll
    for (int mi = 0; mi < 4; mi++)
#pragma unroll
        for (int ni = 0; ni < 4; ni++)
#pragma unroll
            for (int q = 0; q < 4; q++) acc[mi][ni][q] = 0.f;

    auto fetchA = [&](int kk, uint4* pr) {
        const __nv_bfloat16* ap = A + (size_t)(rowBase + ar_) * 256 + kk + ah_ * 16;
        pr[0] = *(const uint4*)ap;
        pr[1] = *(const uint4*)(ap + 8);
    };
    auto fetchB = [&](int kk, uint4* pr) {
        const __nv_bfloat16* bp = B + (size_t)(kk + 2 * bkp) * 256 + colBase + bn0;
        pr[0] = *(const uint4*)bp;
        pr[1] = *(const uint4*)(bp + 256);
    };
    auto storeA = [&](const uint4* pr, int bf) {
        unsigned* dst = &As[bf][ar_][ah_ * 8];
        *(uint4*)&dst[0] = pr[0];
        *(uint4*)&dst[4] = pr[1];
    };
    auto storeB = [&](const uint4* pr, int bf) {
        unsigned e[4] = {pr[0].x, pr[0].y, pr[0].z, pr[0].w};
        unsigned o[4] = {pr[1].x, pr[1].y, pr[1].z, pr[1].w};
#pragma unroll
        for (int j = 0; j < 4; j++) {
            Bs[bf][bn0 + 2 * j][bkp]     = __byte_perm(e[j], o[j], 0x5410);
            Bs[bf][bn0 + 2 * j + 1][bkp] = __byte_perm(e[j], o[j], 0x7632);
        }
    };

    uint4 pA[2], pB[2];
    fetchA(0, pA); fetchB(0, pB);
    storeA(pA, 0); storeB(pB, 0);
    __syncthreads();

    int buf = 0;
    for (int k0 = 0; k0 < 256; k0 += 32) {
        bool nxt = k0 < 224;
        if (nxt) { fetchA(k0 + 32, pA); fetchB(k0 + 32, pB); }
#pragma unroll
        for (int ks = 0; ks < 2; ks++) {
            int kb = ks * 8;
            unsigned arf[4][4], brf[4][2];
#pragma unroll
            for (int mi = 0; mi < 4; mi++) {
                int r = wr * 64 + mi * 16 + r0;
                arf[mi][0] = As[buf][r][kb + kq];
                arf[mi][1] = As[buf][r + 8][kb + kq];
                arf[mi][2] = As[buf][r][kb + kq + 4];
                arf[mi][3] = As[buf][r + 8][kb + kq + 4];
            }
#pragma unroll
            for (int ni = 0; ni < 4; ni++) {
                int n = wc * 32 + ni * 8 + r0;
                brf[ni][0] = Bs[buf][n][kb + kq];
                brf[ni][1] = Bs[buf][n][kb + kq + 4];
            }
#pragma unroll
            for (int mi = 0; mi < 4; mi++)
#pragma unroll
                for (int ni = 0; ni < 4; ni++) mma16(acc[mi][ni], arf[mi], brf[ni]);
        }
        if (nxt) { storeA(pA, buf ^ 1); storeB(pB, buf ^ 1); }
        __syncthreads();
        buf ^= 1;
    }

#pragma unroll
    for (int mi = 0; mi < 4; mi++) {
#pragma unroll
        for (int ni = 0; ni < 4; ni++) {
            int rr = rowBase + wr * 64 + mi * 16 + r0;
            int cc = colBase + wc * 32 + ni * 8 + kq * 2;
#pragma unroll
            for (int hf = 0; hf < 2; hf++) {
                int r = rr + hf * 8;
                float v0 = cM * acc[mi][ni][hf * 2];
                float v1 = cM * acc[mi][ni][hf * 2 + 1];
                if (AEp) {
                    float2 f = unpackbf(*(const unsigned*)(AEp + (size_t)r * 256 + cc));
                    v0 += cA * f.x; v1 += cA * f.y;
                }
                *(unsigned*)(C + (size_t)r * 256 + cc) = packbf(v0, v1);
            }
        }
    }
}

// ---------------- flash attn3 @ v, double-buffered K/V ----------------
// grid (4,32), 128 thr; smem u32: Qs@0, Ks[2]@2304, Vt[2]@6912, Ps@11520 (13824 u32)
__global__ __launch_bounds__(128) void k_flash() {
    int rt = blockIdx.x, bh = blockIdx.y;
    extern __shared__ unsigned sm[];
    unsigned* Qs  = sm;
    unsigned* Ks0 = sm + 2304;
    unsigned* Vt0 = sm + 6912;
    unsigned* Ps  = sm + 11520;
    const __nv_bfloat16* qlp = g_ql + (size_t)bh * 16384 + (size_t)rt * 64 * 64;
    const __nv_bfloat16* kp  = g_k + ((size_t)bh << 18);
    const __nv_bfloat16* vp  = g_v + ((size_t)bh << 18);
    int tid = threadIdx.x, lane = tid & 31, w = tid >> 5;
    int r0 = lane >> 2, kq = lane & 3;
    int wrow = w * 16;
    int kr_ = tid >> 1, kh_ = tid & 1;

    auto fetchK = [&](int n0, uint4* pk) {
        const __nv_bfloat16* ap = kp + (size_t)(n0 + kr_) * 64 + kh_ * 32;
#pragma unroll
        for (int i = 0; i < 4; i++) pk[i] = ((const uint4*)ap)[i];
    };
    auto storeK = [&](const uint4* pk, int bf) {
        unsigned* dst = Ks0 + bf * 2304 + kr_ * 36 + kh_ * 16;
#pragma unroll
        for (int i = 0; i < 4; i++) *(uint4*)&dst[i * 4] = pk[i];
    };
    auto fetchV = [&](int n0, uint4* pv) {
#pragma unroll
        for (int it = 0; it < 2; it++) {
            int i = tid + it * 128;
            int sp = i >> 3, dg = i & 7;
            const __nv_bfloat16* ap = vp + (size_t)(n0 + 2 * sp) * 64 + dg * 8;
            pv[it * 2]     = *(const uint4*)ap;
            pv[it * 2 + 1] = *(const uint4*)(ap + 64);
        }
    };
    auto storeV = [&](const uint4* pv, int bf) {
        unsigned* Vt = Vt0 + bf * 2304;
#pragma unroll
        for (int it = 0; it < 2; it++) {
            int i = tid + it * 128;
            int sp = i >> 3, dg = i & 7;
            unsigned av[4] = {pv[it*2].x, pv[it*2].y, pv[it*2].z, pv[it*2].w};
            unsigned bv[4] = {pv[it*2+1].x, pv[it*2+1].y, pv[it*2+1].z, pv[it*2+1].w};
#pragma unroll
            for (int q2 = 0; q2 < 4; q2++) {
                int d0 = dg * 8 + q2 * 2;
                Vt[d0 * 36 + sp]       = __byte_perm(av[q2], bv[q2], 0x5410);
                Vt[(d0 + 1) * 36 + sp] = __byte_perm(av[q2], bv[q2], 0x7632);
            }
        }
    };

    {   // Q tile
        const __nv_bfloat16* ap = qlp + kr_ * 64 + kh_ * 32;
        unsigned* dst = &Qs[kr_ * 36 + kh_ * 16];
#pragma unroll
        for (int i = 0; i < 4; i++) *(uint4*)&dst[i * 4] = ((const uint4*)ap)[i];
    }
    uint4 pk[4], pv[4];
    fetchK(0, pk); fetchV(0, pv);
    storeK(pk, 0); storeV(pv, 0);
    __syncthreads();

    float O[8][4];
#pragma unroll
    for (int j = 0; j < 8; j++)
#pragma unroll
        for (int q = 0; q < 4; q++) O[j][q] = 0.f;
    float m0 = -1e30f, m1 = -1e30f, l0 = 0.f, l1 = 0.f;

    int buf = 0;
    for (int n0 = 0; n0 < 4096; n0 += 64) {
        bool nxt = n0 < 4032;
        if (nxt) { fetchK(n0 + 64, pk); fetchV(n0 + 64, pv); }
        unsigned* Ks = Ks0 + buf * 2304;
        unsigned* Vt = Vt0 + buf * 2304;

        float sc[8][4];
#pragma unroll
        for (int j = 0; j < 8; j++)
#pragma unroll
            for (int q = 0; q < 4; q++) sc[j][q] = 0.f;
#pragma unroll
        for (int ks = 0; ks < 4; ks++) {
            int kb = ks * 8;
            unsigned a[4];
            a[0] = Qs[(wrow + r0) * 36 + kb + kq];
            a[1] = Qs[(wrow + r0 + 8) * 36 + kb + kq];
            a[2] = Qs[(wrow + r0) * 36 + kb + kq + 4];
            a[3] = Qs[(wrow + r0 + 8) * 36 + kb + kq + 4];
#pragma unroll
            for (int j = 0; j < 8; j++) {
                unsigned b[2] = { Ks[(j * 8 + r0) * 36 + kb + kq],
                                  Ks[(j * 8 + r0) * 36 + kb + kq + 4] };
                mma16(sc[j], a, b);
            }
        }
        float tm0 = -1e30f, tm1 = -1e30f;
#pragma unroll
        for (int j = 0; j < 8; j++) {
            tm0 = fmaxf(tm0, fmaxf(sc[j][0], sc[j][1]));
            tm1 = fmaxf(tm1, fmaxf(sc[j][2], sc[j][3]));
        }
        tm0 = fmaxf(tm0, __shfl_xor_sync(0xffffffffu, tm0, 1));
        tm0 = fmaxf(tm0, __shfl_xor_sync(0xffffffffu, tm0, 2));
        tm1 = fmaxf(tm1, __shfl_xor_sync(0xffffffffu, tm1, 1));
        tm1 = fmaxf(tm1, __shfl_xor_sync(0xffffffffu, tm1, 2));
        float mn0 = fmaxf(m0, tm0), mn1 = fmaxf(m1, tm1);
        float al0 = __expf(m0 - mn0), al1 = __expf(m1 - mn1);
        float ts0 = 0.f, ts1 = 0.f;
#pragma unroll
        for (int j = 0; j < 8; j++) {
            sc[j][0] = __expf(sc[j][0] - mn0); sc[j][1] = __expf(sc[j][1] - mn0);
            sc[j][2] = __expf(sc[j][2] - mn1); sc[j][3] = __expf(sc[j][3] - mn1);
            ts0 += sc[j][0] + sc[j][1];
            ts1 += sc[j][2] + sc[j][3];
        }
        ts0 += __shfl_xor_sync(0xffffffffu, ts0, 1); ts0 += __shfl_xor_sync(0xffffffffu, ts0, 2);
        ts1 += __shfl_xor_sync(0xffffffffu, ts1, 1); ts1 += __shfl_xor_sync(0xffffffffu, ts1, 2);
        l0 = l0 * al0 + ts0; l1 = l1 * al1 + ts1;
        m0 = mn0; m1 = mn1;
#pragma unroll
        for (int j = 0; j < 8; j++) {
            O[j][0] *= al0; O[j][1] *= al0; O[j][2] *= al1; O[j][3] *= al1;
        }
#pragma unroll
        for (int j = 0; j < 8; j++) {
            Ps[(wrow + r0) * 36 + j * 4 + kq]     = packbf(sc[j][0], sc[j][1]);
            Ps[(wrow + r0 + 8) * 36 + j * 4 + kq] = packbf(sc[j][2], sc[j][3]);
        }
        __syncwarp();
#pragma unroll
        for (int ks = 0; ks < 4; ks++) {
            int kb = ks * 8;
            unsigned a[4];
            a[0] = Ps[(wrow + r0) * 36 + kb + kq];
            a[1] = Ps[(wrow + r0 + 8) * 36 + kb + kq];
            a[2] = Ps[(wrow + r0) * 36 + kb + kq + 4];
            a[3] = Ps[(wrow + r0 + 8) * 36 + kb + kq + 4];
#pragma unroll
            for (int j = 0; j < 8; j++) {
                unsigned b[2] = { Vt[(j * 8 + r0) * 36 + kb + kq],
                                  Vt[(j * 8 + r0) * 36 + kb + kq + 4] };
                mma16(O[j], a, b);
            }
        }
        __syncwarp();
        if (nxt) { storeK(pk, buf ^ 1); storeV(pv, buf ^ 1); }
        __syncthreads();
        buf ^= 1;
    }
    float il0 = 1.f / l0, il1 = 1.f / l1;
    __nv_bfloat16* op = g_a3v + (size_t)bh * 16384 + (size_t)rt * 64 * 64;
#pragma unroll
    for (int j = 0; j < 8; j++) {
        *(unsigned*)(op + (wrow + r0) * 64 + j * 8 + kq * 2)     = packbf(O[j][0] * il0, O[j][1] * il0);
        *(unsigned*)(op + (wrow + r0 + 8) * 64 + j * 8 + kq * 2) = packbf(O[j][2] * il1, O[j][3] * il1);
    }
}

// ---------------- fused attn1 (unchanged from R5) ----------------
__global__ __launch_bounds__(256, 1) void k_attn1() {
    int bx = blockIdx.x, bh = blockIdx.y;
    extern __shared__ unsigned sm[];
    unsigned* KLs = sm;
    unsigned* Qs  = sm + 9216;
    unsigned* Ps  = sm + 13824;
    unsigned* Wt  = sm;
    const __nv_bfloat16* qp  = g_q + ((size_t)bh << 18) + (size_t)bx * 128 * 64;
    const __nv_bfloat16* klp = g_kl + (size_t)bh * 16384;
    const __nv_bfloat16* wp  = g_wm + (size_t)bh * 16384;
    int tid = threadIdx.x, lane = tid & 31, w = tid >> 5;
    int r0 = lane >> 2, kq = lane & 3;
    int wrow = w * 16;

    {
        int r = tid >> 1, h = tid & 1;
        const __nv_bfloat16* ap = qp + r * 64 + h * 32;
        unsigned* dst = &Qs[r * 36 + h * 16];
#pragma unroll
        for (int i = 0; i < 4; i++) *(uint4*)&dst[i * 4] = ((const uint4*)ap)[i];
    }
    {
        int r = tid;
        const __nv_bfloat16* ap = klp + r * 64;
        unsigned* dst = &KLs[r * 36];
#pragma unroll
        for (int i = 0; i < 8; i++) *(uint4*)&dst[i * 4] = ((const uint4*)ap)[i];
    }
    __syncthreads();

    float sc[32][4];
#pragma unroll
    for (int j = 0; j < 32; j++)
#pragma unroll
        for (int q = 0; q < 4; q++) sc[j][q] = 0.f;
#pragma unroll
    for (int ks = 0; ks < 4; ks++) {
        int kb = ks * 8;
        unsigned a[4];
        a[0] = Qs[(wrow + r0) * 36 + kb + kq];
        a[1] = Qs[(wrow + r0 + 8) * 36 + kb + kq];
        a[2] = Qs[(wrow + r0) * 36 + kb + kq + 4];
        a[3] = Qs[(wrow + r0 + 8) * 36 + kb + kq + 4];
#pragma unroll
        for (int j = 0; j < 32; j++) {
            unsigned b[2] = { KLs[(j * 8 + r0) * 36 + kb + kq],
                              KLs[(j * 8 + r0) * 36 + kb + kq + 4] };
            mma16(sc[j], a, b);
        }
    }
    float m0 = -1e30f, m1 = -1e30f;
#pragma unroll
    for (int j = 0; j < 32; j++) {
        m0 = fmaxf(m0, fmaxf(sc[j][0], sc[j][1]));
        m1 = fmaxf(m1, fmaxf(sc[j][2], sc[j][3]));
    }
    m0 = fmaxf(m0, __shfl_xor_sync(0xffffffffu, m0, 1));
    m0 = fmaxf(m0, __shfl_xor_sync(0xffffffffu, m0, 2));
    m1 = fmaxf(m1, __shfl_xor_sync(0xffffffffu, m1, 1));
    m1 = fmaxf(m1, __shfl_xor_sync(0xffffffffu, m1, 2));
    float l0 = 0.f, l1 = 0.f;
#pragma unroll
    for (int j = 0; j < 32; j++) {
        sc[j][0] = __expf(sc[j][0] - m0); sc[j][1] = __expf(sc[j][1] - m0);
        sc[j][2] = __expf(sc[j][2] - m1); sc[j][3] = __expf(sc[j][3] - m1);
        l0 += sc[j][0] + sc[j][1];
        l1 += sc[j][2] + sc[j][3];
    }
    l0 += __shfl_xor_sync(0xffffffffu, l0, 1); l0 += __shfl_xor_sync(0xffffffffu, l0, 2);
    l1 += __shfl_xor_sync(0xffffffffu, l1, 1); l1 += __shfl_xor_sync(0xffffffffu, l1, 2);

    __syncthreads();
#pragma unroll
    for (int it = 0; it < 4; it++) {
        int i = tid + it * 256;
        int mp = i >> 3, dg = i & 7;
        const __nv_bfloat16* ap = wp + (size_t)(2 * mp) * 64 + dg * 8;
        uint4 ua = *(const uint4*)ap;
        uint4 ub = *(const uint4*)(ap + 64);
        unsigned av[4] = {ua.x, ua.y, ua.z, ua.w};
        unsigned bv[4] = {ub.x, ub.y, ub.z, ub.w};
#pragma unroll
        for (int q2 = 0; q2 < 4; q2++) {
            int d0 = dg * 8 + q2 * 2;
            Wt[d0 * 132 + mp]       = __byte_perm(av[q2], bv[q2], 0x5410);
            Wt[(d0 + 1) * 132 + mp] = __byte_perm(av[q2], bv[q2], 0x7632);
        }
    }
    __syncthreads();

    float O[8][4];
#pragma unroll
    for (int j = 0; j < 8; j++)
#pragma unroll
        for (int q = 0; q < 4; q++) O[j][q] = 0.f;

#pragma unroll
    for (int ch = 0; ch < 4; ch++) {
#pragma unroll
        for (int jj = 0; jj < 8; jj++) {
            int j = ch * 8 + jj;
            Ps[(wrow + r0) * 36 + jj * 4 + kq]     = packbf(sc[j][0], sc[j][1]);
            Ps[(wrow + r0 + 8) * 36 + jj * 4 + kq] = packbf(sc[j][2], sc[j][3]);
        }
        __syncwarp();
#pragma unroll
        for (int ks = 0; ks < 4; ks++) {
            int kb = ks * 8;
            unsigned a[4];
            a[0] = Ps[(wrow + r0) * 36 + kb + kq];
            a[1] = Ps[(wrow + r0 + 8) * 36 + kb + kq];
            a[2] = Ps[(wrow + r0) * 36 + kb + kq + 4];
            a[3] = Ps[(wrow + r0 + 8) * 36 + kb + kq + 4];
#pragma unroll
            for (int j = 0; j < 8; j++) {
                unsigned b[2] = { Wt[(j * 8 + r0) * 132 + ch * 32 + kb + kq],
                                  Wt[(j * 8 + r0) * 132 + ch * 32 + kb + kq + 4] };
                mma16(O[j], a, b);
            }
        }
        __syncwarp();
    }

    float il0 = 1.f / l0, il1 = 1.f / l1;
    __nv_bfloat16* op = g_outh + ((size_t)bh << 18) + (size_t)bx * 128 * 64;
#pragma unroll
    for (int j = 0; j < 8; j++) {
        *(unsigned*)(op + (wrow + r0) * 64 + j * 8 + kq * 2)     = packbf(O[j][0] * il0, O[j][1] * il0);
        *(unsigned*)(op + (wrow + r0 + 8) * 64 + j * 8 + kq * 2) = packbf(O[j][2] * il1, O[j][3] * il1);
    }
}

// ---------------- host orchestration ----------------
extern "C" void kernel_launch(void* const* d_in, const int* in_sizes, int n_in,
                              void* d_out, int out_size) {
    const float* x      = (const float*)d_in[0];
    const float* gamma  = (const float*)d_in[1];
    const float* beta   = (const float*)d_in[2];
    const float* w_qkv  = (const float*)d_in[3];
    const float* w_out  = (const float*)d_in[4];
    const float* b_out  = (const float*)d_in[5];
    const float* conv_w = (const float*)d_in[6];
    float* out = (float*)d_out;

    void* tp;
    cudaGetSymbolAddress(&tp, g_ql);   __nv_bfloat16* p_ql  = (__nv_bfloat16*)tp;
    cudaGetSymbolAddress(&tp, g_kl);   __nv_bfloat16* p_kl  = (__nv_bfloat16*)tp;
    cudaGetSymbolAddress(&tp, g_a2f);  float*         p_a2f = (float*)tp;
    cudaGetSymbolAddress(&tp, g_a2h);  __nv_bfloat16* p_a2h = (__nv_bfloat16*)tp;
    cudaGetSymbolAddress(&tp, g_z);    __nv_bfloat16* p_z   = (__nv_bfloat16*)tp;
    cudaGetSymbolAddress(&tp, g_zn);   __nv_bfloat16* p_zn  = (__nv_bfloat16*)tp;
    cudaGetSymbolAddress(&tp, g_az);   __nv_bfloat16* p_az  = (__nv_bfloat16*)tp;
    cudaGetSymbolAddress(&tp, g_w1);   __nv_bfloat16* p_w1  = (__nv_bfloat16*)tp;
    cudaGetSymbolAddress(&tp, g_w2);   __nv_bfloat16* p_w2  = (__nv_bfloat16*)tp;
    cudaGetSymbolAddress(&tp, g_a3v);  __nv_bfloat16* p_a3v = (__nv_bfloat16*)tp;
    cudaGetSymbolAddress(&tp, g_wm);   __nv_bfloat16* p_wm  = (__nv_bfloat16*)tp;

    cudaFuncSetAttribute(k_flash, cudaFuncAttributeMaxDynamicSharedMemorySize, 55296);
    cudaFuncSetAttribute(k_attn1, cudaFuncAttributeMaxDynamicSharedMemorySize, 73728);

    k_lnstats<<<Bb * Nn, 256>>>(x);

    // qkv = LN(x) @ w_qkv -> scatter bf16 q/k/v
    tgemm<<<dim3(24, 128, 1), 256>>>(x, w_qkv, nullptr, 512, 512, 1536, 0,
        0, 0, 0, 1, 0, 1, 1.f, 0.f, nullptr, nullptr, nullptr, gamma, beta);

    k_land<<<(2 * BHc * Mm * 32) / 256, 256>>>();

    // a2f = ql @ kl^T (fp32 out), then softmax fp32
    tgemm<<<dim3(4, 2, 32), 256>>>(p_ql, p_kl, p_a2f, 64, 64, 64, 256,
        (long)Mm * Dd, (long)Mm * Dd, (long)Mm * Mm, 0, 2, 2, 1.f, 0.f,
        nullptr, nullptr, nullptr, nullptr, nullptr);
    k_softmax1<<<BHc * Mm, 256>>>(p_a2f);

    k_sums<<<BHc, 256>>>(p_a2f);
    k_z0<<<(BHc * Mm * Mm / 2) / 256, 256>>>();

    // flash attn3 @ v
    k_flash<<<dim3(4, 32), 128, 55296>>>();

    // Newton-Schulz (bf16, single-wave 128-CTA GEMMs)
    __nv_bfloat16* zc = p_z; __nv_bfloat16* zo = p_zn;
    for (int it = 0; it < 6; it++) {
        ngemm<<<dim3(2, 2, 32), 256>>>(p_a2h, zc, p_az, 1.f, 0.f, nullptr);
        ngemm<<<dim3(2, 2, 32), 256>>>(p_az, p_az, p_w1, -1.f, 7.f, p_az);
        ngemm<<<dim3(2, 2, 32), 256>>>(p_az, p_w1, p_w2, -1.f, 15.f, p_az);
        ngemm<<<dim3(2, 2, 32), 256>>>(zc, p_w2, zo, -0.25f, 3.25f, zc);
        __nv_bfloat16* t = zc; zc = zo; zo = t;
    }

    // wm = Z @ a3v
    tgemm<<<dim3(1, 2, 32), 256>>>(zc, p_a3v, p_wm, 256, 256, 64, 64,
        (long)Mm * Mm, (long)Mm * Dd, (long)Mm * Dd, 0, 1, 0, 1.f, 0.f,
        nullptr, nullptr, nullptr, nullptr, nullptr);

    // fused attn1 -> outh (bf16)
    k_attn1<<<dim3(32, 32), 256, 73728>>>();

    // conv residual add
    k_conv2<<<dim3(32, 32), 256>>>(conv_w);

    // final: out = merge(outh) @ w_out + b_out + x
    tgemm<<<dim3(8, 128, 1), 256>>>(nullptr, w_out, out, 512, 512, 512, 512,
        0, 0, 0, 2, 0, 2, 1.f, 0.f, nullptr, b_out, x, nullptr, nullptr);
}